// round 2
// baseline (speedup 1.0000x reference)
#include <cuda_runtime.h>
#include <math.h>

// ---------------- problem constants ----------------
#define BB   2
#define SS   2048
#define HH   1024
#define NHH  16
#define DHH  64
#define FFD  4096
#define MM   (BB*SS)     // 4096 rows

// ---------------- scratch (static device globals; no allocation) -----------
__device__ float g_x  [(size_t)MM * HH];        // running residual
__device__ float g_h  [(size_t)MM * HH];        // layernorm output
__device__ float g_qkv[(size_t)MM * 3 * HH];    // qkv projection
__device__ float g_ctx[(size_t)MM * HH];        // attention context
__device__ float g_ff [(size_t)MM * FFD];       // mlp hidden

// ---------------- small helpers ----------------
__device__ __forceinline__ float warp_sum(float v) {
#pragma unroll
    for (int o = 16; o; o >>= 1) v += __shfl_xor_sync(0xffffffffu, v, o);
    return v;
}

// ---------------- copy input -> g_x ----------------
__global__ void copy_kernel(const float* __restrict__ in, float* __restrict__ out, int n4) {
    int i = blockIdx.x * blockDim.x + threadIdx.x;
    if (i < n4) ((float4*)out)[i] = ((const float4*)in)[i];
}

// ---------------- layernorm: 1 block (256 thr) per row of 1024 -------------
__global__ void ln_kernel(const float* __restrict__ x, const float* __restrict__ w,
                          const float* __restrict__ b, float* __restrict__ o) {
    __shared__ float r1[8], r2[8];
    const int row = blockIdx.x, tid = threadIdx.x;
    const float4 v = *(const float4*)(x + (size_t)row * HH + tid * 4);
    float s = v.x + v.y + v.z + v.w;
    s = warp_sum(s);
    if ((tid & 31) == 0) r1[tid >> 5] = s;
    __syncthreads();
    float mean = 0.f;
#pragma unroll
    for (int i = 0; i < 8; i++) mean += r1[i];
    mean *= (1.f / (float)HH);
    const float d0 = v.x - mean, d1 = v.y - mean, d2 = v.z - mean, d3 = v.w - mean;
    float sq = d0 * d0 + d1 * d1 + d2 * d2 + d3 * d3;
    sq = warp_sum(sq);
    if ((tid & 31) == 0) r2[tid >> 5] = sq;
    __syncthreads();
    float var = 0.f;
#pragma unroll
    for (int i = 0; i < 8; i++) var += r2[i];
    var *= (1.f / (float)HH);
    const float rstd = rsqrtf(var + 1e-5f);
    const float4 wv = *(const float4*)(w + tid * 4);
    const float4 bv = *(const float4*)(b + tid * 4);
    float4 ov;
    ov.x = d0 * rstd * wv.x + bv.x;
    ov.y = d1 * rstd * wv.y + bv.y;
    ov.z = d2 * rstd * wv.z + bv.z;
    ov.w = d3 * rstd * wv.w + bv.w;
    *(float4*)(o + (size_t)row * HH + tid * 4) = ov;
}

// ---------------- SGEMM (TN): C[M,N] = A[M,K] * W[N,K]^T + epilogue --------
// EPI 0: +bias     EPI 1: gelu(+bias)     EPI 2: +bias + res
template <int EPI>
__global__ void sgemm_tn(const float* __restrict__ A, const float* __restrict__ W,
                         const float* __restrict__ bias, const float* __restrict__ res,
                         float* __restrict__ C, int M, int N, int K) {
    __shared__ float As[16][68];
    __shared__ float Bs[16][68];
    const int tid = threadIdx.x;
    const int tx = tid & 15, ty = tid >> 4;
    const int mb = blockIdx.y << 6, nb = blockIdx.x << 6;
    const int lr = tid >> 2;          // 0..63 row within tile
    const int lk = (tid & 3) << 2;    // 0,4,8,12 k offset
    const float* Ag = A + (size_t)(mb + lr) * K + lk;
    const float* Wg = W + (size_t)(nb + lr) * K + lk;
    float acc[4][4] = {};
    for (int k0 = 0; k0 < K; k0 += 16) {
        const float4 a4 = *(const float4*)(Ag + k0);
        const float4 b4 = *(const float4*)(Wg + k0);
        __syncthreads();
        As[lk + 0][lr] = a4.x; As[lk + 1][lr] = a4.y; As[lk + 2][lr] = a4.z; As[lk + 3][lr] = a4.w;
        Bs[lk + 0][lr] = b4.x; Bs[lk + 1][lr] = b4.y; Bs[lk + 2][lr] = b4.z; Bs[lk + 3][lr] = b4.w;
        __syncthreads();
#pragma unroll
        for (int kk = 0; kk < 16; ++kk) {
            const float4 av = *(const float4*)(&As[kk][ty << 2]);
            const float4 bv = *(const float4*)(&Bs[kk][tx << 2]);
            const float a_[4] = {av.x, av.y, av.z, av.w};
            const float b_[4] = {bv.x, bv.y, bv.z, bv.w};
#pragma unroll
            for (int i = 0; i < 4; i++)
#pragma unroll
                for (int j = 0; j < 4; j++) acc[i][j] += a_[i] * b_[j];
        }
    }
    const float4 bia = *(const float4*)(bias + nb + (tx << 2));
    const float bi[4] = {bia.x, bia.y, bia.z, bia.w};
#pragma unroll
    for (int i = 0; i < 4; i++) {
        const size_t ro = (size_t)(mb + (ty << 2) + i) * N + nb + (tx << 2);
        float o[4];
#pragma unroll
        for (int j = 0; j < 4; j++) {
            float v = acc[i][j] + bi[j];
            if (EPI == 1) v = 0.5f * v * (1.0f + erff(v * 0.70710678118654752f));
            if (EPI == 2) v += res[ro + j];
            o[j] = v;
        }
        *(float4*)(C + ro) = make_float4(o[0], o[1], o[2], o[3]);
    }
}

// ---------------- flash attention (fp32, causal, ALiBi) --------------------
// grid: (S/64, NH, B), block 256 (16x16), dynamic smem.
// scores_final = alibi[b,h,k] + (q.k)/8  (layer_number cancels)
#define FLASH_SMEM ((64*65*2 + 64*64*2 + 64) * 4)
__global__ void flash_kernel(const float* __restrict__ qkv,
                             const float* __restrict__ alibi,
                             float* __restrict__ ctx) {
    extern __shared__ float smf[];
    float* Qs = smf;              // [64][65]
    float* Ks = Qs + 64 * 65;     // [64][65]
    float* Vs = Ks + 64 * 65;     // [64][64]
    float* Ps = Vs + 64 * 64;     // [64][64]
    float* al = Ps + 64 * 64;     // [64]

    const int qt = blockIdx.x, hh = blockIdx.y, bb = blockIdx.z;
    const int tid = threadIdx.x;
    const int tx = tid & 15, ty = tid >> 4;
    const int qbase = qt * 64;

    const float* qg  = qkv + (size_t)bb * SS * (3 * HH) + hh * DHH;
    const float* kg  = qg + HH;
    const float* vg  = qg + 2 * HH;
    const float* alg = alibi + ((size_t)bb * NHH + hh) * SS;

    for (int f = tid; f < 1024; f += 256) {
        const int r = f >> 4, d = (f & 15) << 2;
        const float4 q4 = *(const float4*)(qg + (size_t)(qbase + r) * (3 * HH) + d);
        Qs[r * 65 + d + 0] = q4.x; Qs[r * 65 + d + 1] = q4.y;
        Qs[r * 65 + d + 2] = q4.z; Qs[r * 65 + d + 3] = q4.w;
    }

    float mx[4], lsum[4], acc[4][4];
#pragma unroll
    for (int i = 0; i < 4; i++) {
        mx[i] = -INFINITY; lsum[i] = 0.f;
#pragma unroll
        for (int j = 0; j < 4; j++) acc[i][j] = 0.f;
    }

    for (int jt = 0; jt <= qt; ++jt) {
        const int kbase = jt * 64;
        __syncthreads();   // protects Qs (first iter) and Ks/Vs/Ps reuse
        for (int f = tid; f < 1024; f += 256) {
            const int r = f >> 4, d = (f & 15) << 2;
            const float4 k4 = *(const float4*)(kg + (size_t)(kbase + r) * (3 * HH) + d);
            Ks[r * 65 + d + 0] = k4.x; Ks[r * 65 + d + 1] = k4.y;
            Ks[r * 65 + d + 2] = k4.z; Ks[r * 65 + d + 3] = k4.w;
            const float4 v4 = *(const float4*)(vg + (size_t)(kbase + r) * (3 * HH) + d);
            *(float4*)(Vs + r * 64 + d) = v4;
        }
        if (tid < 64) al[tid] = alg[kbase + tid];
        __syncthreads();

        float s[4][4];
#pragma unroll
        for (int i = 0; i < 4; i++)
#pragma unroll
            for (int j = 0; j < 4; j++) s[i][j] = 0.f;

#pragma unroll 4
        for (int d = 0; d < 64; ++d) {
            float qa[4], kb[4];
#pragma unroll
            for (int i = 0; i < 4; i++) qa[i] = Qs[(ty * 4 + i) * 65 + d];
#pragma unroll
            for (int j = 0; j < 4; j++) kb[j] = Ks[(tx * 4 + j) * 65 + d];
#pragma unroll
            for (int i = 0; i < 4; i++)
#pragma unroll
                for (int j = 0; j < 4; j++) s[i][j] += qa[i] * kb[j];
        }

        const bool diag = (jt == qt);
#pragma unroll
        for (int i = 0; i < 4; i++) {
            const int qr = qbase + ty * 4 + i;
            float lm = -INFINITY;
#pragma unroll
            for (int j = 0; j < 4; j++) {
                const int kc = kbase + tx * 4 + j;
                float sc = s[i][j] * 0.125f + al[tx * 4 + j];
                if (diag && kc > qr) sc = -1e30f;
                s[i][j] = sc;
                lm = fmaxf(lm, sc);
            }
#pragma unroll
            for (int o = 8; o; o >>= 1) lm = fmaxf(lm, __shfl_xor_sync(0xffffffffu, lm, o, 16));
            const float mn = fmaxf(mx[i], lm);
            const float corr = expf(mx[i] - mn);
            mx[i] = mn;
            float rs = 0.f;
#pragma unroll
            for (int j = 0; j < 4; j++) {
                const float p = expf(s[i][j] - mn);
                rs += p;
                Ps[(ty * 4 + i) * 64 + tx * 4 + j] = p;
            }
#pragma unroll
            for (int o = 8; o; o >>= 1) rs += __shfl_xor_sync(0xffffffffu, rs, o, 16);
            lsum[i] = lsum[i] * corr + rs;
#pragma unroll
            for (int j = 0; j < 4; j++) acc[i][j] *= corr;
        }
        __syncthreads();

#pragma unroll 4
        for (int c = 0; c < 64; ++c) {
            const float4 v4 = *(const float4*)(Vs + c * 64 + tx * 4);
#pragma unroll
            for (int i = 0; i < 4; i++) {
                const float p = Ps[(ty * 4 + i) * 64 + c];
                acc[i][0] += p * v4.x; acc[i][1] += p * v4.y;
                acc[i][2] += p * v4.z; acc[i][3] += p * v4.w;
            }
        }
    }

#pragma unroll
    for (int i = 0; i < 4; i++) {
        const float inv = 1.f / lsum[i];
        const float4 o = make_float4(acc[i][0] * inv, acc[i][1] * inv,
                                     acc[i][2] * inv, acc[i][3] * inv);
        *(float4*)(ctx + ((size_t)bb * SS + qbase + ty * 4 + i) * HH + hh * DHH + tx * 4) = o;
    }
}

// ---------------- driver ----------------
extern "C" void kernel_launch(void* const* d_in, const int* in_sizes, int n_in,
                              void* d_out, int out_size) {
    const float* hs    = (const float*)d_in[0];
    const float* alibi = (const float*)d_in[1];
    const float* qkvw  = (const float*)d_in[2];
    const float* qkvb  = (const float*)d_in[3];
    const float* dw    = (const float*)d_in[4];
    const float* db    = (const float*)d_in[5];
    const float* w1    = (const float*)d_in[6];
    const float* b1    = (const float*)d_in[7];
    const float* w2    = (const float*)d_in[8];
    const float* b2    = (const float*)d_in[9];
    const float* l1w   = (const float*)d_in[10];
    const float* l1b   = (const float*)d_in[11];
    const float* l2w   = (const float*)d_in[12];
    const float* l2b   = (const float*)d_in[13];
    float* out = (float*)d_out;

    float *x, *h, *qkv, *ctx, *ff;
    cudaGetSymbolAddress((void**)&x,   g_x);
    cudaGetSymbolAddress((void**)&h,   g_h);
    cudaGetSymbolAddress((void**)&qkv, g_qkv);
    cudaGetSymbolAddress((void**)&ctx, g_ctx);
    cudaGetSymbolAddress((void**)&ff,  g_ff);

    cudaFuncSetAttribute(flash_kernel, cudaFuncAttributeMaxDynamicSharedMemorySize, FLASH_SMEM);

    const int n4 = MM * HH / 4;
    copy_kernel<<<(n4 + 255) / 256, 256>>>(hs, x, n4);

    for (int l = 0; l < 2; ++l) {
        ln_kernel<<<MM, 256>>>(x, l1w + l * HH, l1b + l * HH, h);
        sgemm_tn<0><<<dim3(3 * HH / 64, MM / 64), 256>>>(
            h, qkvw + (size_t)l * 3 * HH * HH, qkvb + (size_t)l * 3 * HH, nullptr,
            qkv, MM, 3 * HH, HH);
        flash_kernel<<<dim3(SS / 64, NHH, BB), 256, FLASH_SMEM>>>(qkv, alibi, ctx);
        sgemm_tn<2><<<dim3(HH / 64, MM / 64), 256>>>(
            ctx, dw + (size_t)l * HH * HH, db + (size_t)l * HH, x,
            x, MM, HH, HH);
        ln_kernel<<<MM, 256>>>(x, l2w + l * HH, l2b + l * HH, h);
        sgemm_tn<1><<<dim3(FFD / 64, MM / 64), 256>>>(
            h, w1 + (size_t)l * FFD * HH, b1 + (size_t)l * FFD, nullptr,
            ff, MM, FFD, HH);
        sgemm_tn<2><<<dim3(HH / 64, MM / 64), 256>>>(
            ff, w2 + (size_t)l * HH * FFD, b2 + (size_t)l * HH, x,
            (l == 1) ? out : x, MM, HH, FFD);
    }
}

// round 3
// speedup vs baseline: 2.0005x; 2.0005x over previous
#include <cuda_runtime.h>
#include <math.h>
#include <stdint.h>

// ---------------- problem constants ----------------
#define BB   2
#define SS   2048
#define HH   1024
#define NHH  16
#define DHH  64
#define FFD  4096
#define MM   (BB*SS)     // 4096 rows

// ---------------- scratch (static device globals; no allocation) -----------
__device__ float g_x  [(size_t)MM * HH];        // running residual
__device__ float g_h  [(size_t)MM * HH];        // layernorm output (tf32-rounded)
__device__ float g_qkv[(size_t)MM * 3 * HH];    // qkv projection
__device__ float g_ctx[(size_t)MM * HH];        // attention context (tf32-rounded)
__device__ float g_ff [(size_t)MM * FFD];       // mlp hidden (tf32-rounded)
#define LWF 12582912                             // floats of weights per layer
__device__ float g_wr [(size_t)2 * LWF];        // tf32-rounded weights

// ---------------- small helpers ----------------
__device__ __forceinline__ float warp_sum(float v) {
#pragma unroll
    for (int o = 16; o; o >>= 1) v += __shfl_xor_sync(0xffffffffu, v, o);
    return v;
}
__device__ __forceinline__ float to_tf32(float x) {
    float y;
    asm("cvt.rna.tf32.f32 %0, %1;" : "=f"(y) : "f"(x));
    return y;
}
__device__ __forceinline__ float gelu_exact(float v) {
    return 0.5f * v * (1.0f + erff(v * 0.70710678118654752f));
}

// ---------------- copy input -> g_x ----------------
__global__ void copy_kernel(const float* __restrict__ in, float* __restrict__ out, int n4) {
    int i = blockIdx.x * blockDim.x + threadIdx.x;
    if (i < n4) ((float4*)out)[i] = ((const float4*)in)[i];
}

// ---------------- tf32 rounding pass (weights) ----------------
__global__ void round_kernel(const float* __restrict__ in, float* __restrict__ out, int n4) {
    int i = blockIdx.x * blockDim.x + threadIdx.x;
    if (i < n4) {
        float4 v = ((const float4*)in)[i];
        v.x = to_tf32(v.x); v.y = to_tf32(v.y); v.z = to_tf32(v.z); v.w = to_tf32(v.w);
        ((float4*)out)[i] = v;
    }
}

// ---------------- layernorm: 1 block (256 thr) per row of 1024 -------------
// Output is tf32-rounded (it only ever feeds tensor-core GEMMs).
__global__ void ln_kernel(const float* __restrict__ x, const float* __restrict__ w,
                          const float* __restrict__ b, float* __restrict__ o) {
    __shared__ float r1[8], r2[8];
    const int row = blockIdx.x, tid = threadIdx.x;
    const float4 v = *(const float4*)(x + (size_t)row * HH + tid * 4);
    float s = v.x + v.y + v.z + v.w;
    s = warp_sum(s);
    if ((tid & 31) == 0) r1[tid >> 5] = s;
    __syncthreads();
    float mean = 0.f;
#pragma unroll
    for (int i = 0; i < 8; i++) mean += r1[i];
    mean *= (1.f / (float)HH);
    const float d0 = v.x - mean, d1 = v.y - mean, d2 = v.z - mean, d3 = v.w - mean;
    float sq = d0 * d0 + d1 * d1 + d2 * d2 + d3 * d3;
    sq = warp_sum(sq);
    if ((tid & 31) == 0) r2[tid >> 5] = sq;
    __syncthreads();
    float var = 0.f;
#pragma unroll
    for (int i = 0; i < 8; i++) var += r2[i];
    var *= (1.f / (float)HH);
    const float rstd = rsqrtf(var + 1e-5f);
    const float4 wv = *(const float4*)(w + tid * 4);
    const float4 bv = *(const float4*)(b + tid * 4);
    float4 ov;
    ov.x = to_tf32(d0 * rstd * wv.x + bv.x);
    ov.y = to_tf32(d1 * rstd * wv.y + bv.y);
    ov.z = to_tf32(d2 * rstd * wv.z + bv.z);
    ov.w = to_tf32(d3 * rstd * wv.w + bv.w);
    *(float4*)(o + (size_t)row * HH + tid * 4) = ov;
}

// ---------------- tf32 tensor-core GEMM (TN) -------------------------------
// C[M,N] = A[M,K] * W[N,K]^T + epilogue.  A, W pre-rounded to tf32.
// 128x128x32 CTA tile, 8 warps (2x4), warp tile 64x32, mma.m16n8k8.
// EPI 0: +bias   EPI 1: tf32(gelu(+bias))   EPI 2: +bias +res
#define GSTAGE (2*128*36)            // floats per pipeline stage (A tile + W tile)
#define GSMEM  (2*GSTAGE*4)          // bytes of dynamic smem (2 stages)

template <int EPI>
__global__ void __launch_bounds__(256, 2) mma_tn(
        const float* __restrict__ A, const float* __restrict__ W,
        const float* __restrict__ bias, const float* __restrict__ res,
        float* __restrict__ C, int M, int N, int K) {
    extern __shared__ float sm[];
    const uint32_t smbase = (uint32_t)__cvta_generic_to_shared(sm);
    const int tid = threadIdx.x;
    const int warp = tid >> 5, lane = tid & 31;
    const int wm = warp >> 2, wn = warp & 3;      // warp grid 2 x 4
    const int g = lane >> 2, t = lane & 3;        // quad row / pos
    const int mb = blockIdx.y << 7, nb = blockIdx.x << 7;

    // global->smem staging: thread loads row ra, 16 consecutive k at offset ka
    const int ra = tid >> 1, ka = (tid & 1) << 4;
    const float* Ag = A + (size_t)(mb + ra) * K + ka;
    const float* Wg = W + (size_t)(nb + ra) * K + ka;
    const uint32_t dA = smbase + (uint32_t)(ra * 36 + ka) * 4u;
    const uint32_t dW = smbase + (uint32_t)(128 * 36 + ra * 36 + ka) * 4u;

    float acc[4][4][4];
#pragma unroll
    for (int a = 0; a < 4; a++)
#pragma unroll
        for (int b = 0; b < 4; b++)
#pragma unroll
            for (int c = 0; c < 4; c++) acc[a][b][c] = 0.f;

    const int nk = K >> 5;
    auto issue = [&](int kt, int s) {
        const float* ap = Ag + (kt << 5);
        const float* wp = Wg + (kt << 5);
        const uint32_t da = dA + (uint32_t)s * (GSTAGE * 4);
        const uint32_t dw = dW + (uint32_t)s * (GSTAGE * 4);
#pragma unroll
        for (int i = 0; i < 4; i++) {
            asm volatile("cp.async.cg.shared.global [%0], [%1], 16;\n"
                         :: "r"(da + i * 16), "l"(ap + i * 4));
            asm volatile("cp.async.cg.shared.global [%0], [%1], 16;\n"
                         :: "r"(dw + i * 16), "l"(wp + i * 4));
        }
        asm volatile("cp.async.commit_group;\n");
    };

    issue(0, 0);
    if (nk > 1) issue(1, 1);

    const uint32_t* su = (const uint32_t*)sm;
    for (int kt = 0; kt < nk; ++kt) {
        if (kt == nk - 1) asm volatile("cp.async.wait_group 0;\n");
        else              asm volatile("cp.async.wait_group 1;\n");
        __syncthreads();
        const uint32_t* as = su + (kt & 1) * GSTAGE;
        const uint32_t* ws = as + 128 * 36;
#pragma unroll
        for (int kk = 0; kk < 4; kk++) {
            const int k = kk * 8;
            uint32_t af[4][4], bf[4][2];
#pragma unroll
            for (int mt = 0; mt < 4; mt++) {
                const int rb = wm * 64 + mt * 16;
                af[mt][0] = as[(rb + g)     * 36 + k + t];
                af[mt][1] = as[(rb + 8 + g) * 36 + k + t];
                af[mt][2] = as[(rb + g)     * 36 + k + t + 4];
                af[mt][3] = as[(rb + 8 + g) * 36 + k + t + 4];
            }
#pragma unroll
            for (int nt = 0; nt < 4; nt++) {
                const int cb = wn * 32 + nt * 8;
                bf[nt][0] = ws[(cb + g) * 36 + k + t];
                bf[nt][1] = ws[(cb + g) * 36 + k + t + 4];
            }
#pragma unroll
            for (int mt = 0; mt < 4; mt++)
#pragma unroll
                for (int nt = 0; nt < 4; nt++)
                    asm volatile(
                        "mma.sync.aligned.m16n8k8.row.col.f32.tf32.tf32.f32 "
                        "{%0,%1,%2,%3}, {%4,%5,%6,%7}, {%8,%9}, {%0,%1,%2,%3};"
                        : "+f"(acc[mt][nt][0]), "+f"(acc[mt][nt][1]),
                          "+f"(acc[mt][nt][2]), "+f"(acc[mt][nt][3])
                        : "r"(af[mt][0]), "r"(af[mt][1]), "r"(af[mt][2]), "r"(af[mt][3]),
                          "r"(bf[nt][0]), "r"(bf[nt][1]));
        }
        __syncthreads();
        if (kt + 2 < nk) issue(kt + 2, kt & 1);
    }

    // epilogue: c0,c1 -> (row g, cols 2t,2t+1); c2,c3 -> (row g+8)
#pragma unroll
    for (int mt = 0; mt < 4; mt++) {
        const int r0 = mb + wm * 64 + mt * 16 + g;
#pragma unroll
        for (int nt = 0; nt < 4; nt++) {
            const int cb = nb + wn * 32 + nt * 8 + 2 * t;
            const float b0 = bias[cb], b1 = bias[cb + 1];
#pragma unroll
            for (int hh = 0; hh < 2; hh++) {
                const int rr = r0 + hh * 8;
                float v0 = acc[mt][nt][2 * hh + 0] + b0;
                float v1 = acc[mt][nt][2 * hh + 1] + b1;
                const size_t off = (size_t)rr * N + cb;
                if (EPI == 1) { v0 = to_tf32(gelu_exact(v0)); v1 = to_tf32(gelu_exact(v1)); }
                if (EPI == 2) { const float2 rv = *(const float2*)(res + off); v0 += rv.x; v1 += rv.y; }
                *(float2*)(C + off) = make_float2(v0, v1);
            }
        }
    }
}

// ---------------- flash attention (fp32, causal, ALiBi) --------------------
// grid: (S/64, NH, B), block 256 (16x16), dynamic smem.
// scores_final = alibi[b,h,k] + (q.k)/8  (layer_number cancels)
// ctx output tf32-rounded (it only feeds the dense GEMM).
#define FLASH_SMEM ((64*65*2 + 64*64*2 + 64) * 4)
__global__ void flash_kernel(const float* __restrict__ qkv,
                             const float* __restrict__ alibi,
                             float* __restrict__ ctx) {
    extern __shared__ float smf[];
    float* Qs = smf;              // [64][65]
    float* Ks = Qs + 64 * 65;     // [64][65]
    float* Vs = Ks + 64 * 65;     // [64][64]
    float* Ps = Vs + 64 * 64;     // [64][64]
    float* al = Ps + 64 * 64;     // [64]

    const int qt = blockIdx.x, hh = blockIdx.y, bb = blockIdx.z;
    const int tid = threadIdx.x;
    const int tx = tid & 15, ty = tid >> 4;
    const int qbase = qt * 64;

    const float* qg  = qkv + (size_t)bb * SS * (3 * HH) + hh * DHH;
    const float* kg  = qg + HH;
    const float* vg  = qg + 2 * HH;
    const float* alg = alibi + ((size_t)bb * NHH + hh) * SS;

    for (int f = tid; f < 1024; f += 256) {
        const int r = f >> 4, d = (f & 15) << 2;
        const float4 q4 = *(const float4*)(qg + (size_t)(qbase + r) * (3 * HH) + d);
        Qs[r * 65 + d + 0] = q4.x; Qs[r * 65 + d + 1] = q4.y;
        Qs[r * 65 + d + 2] = q4.z; Qs[r * 65 + d + 3] = q4.w;
    }

    float mx[4], lsum[4], acc[4][4];
#pragma unroll
    for (int i = 0; i < 4; i++) {
        mx[i] = -INFINITY; lsum[i] = 0.f;
#pragma unroll
        for (int j = 0; j < 4; j++) acc[i][j] = 0.f;
    }

    for (int jt = 0; jt <= qt; ++jt) {
        const int kbase = jt * 64;
        __syncthreads();
        for (int f = tid; f < 1024; f += 256) {
            const int r = f >> 4, d = (f & 15) << 2;
            const float4 k4 = *(const float4*)(kg + (size_t)(kbase + r) * (3 * HH) + d);
            Ks[r * 65 + d + 0] = k4.x; Ks[r * 65 + d + 1] = k4.y;
            Ks[r * 65 + d + 2] = k4.z; Ks[r * 65 + d + 3] = k4.w;
            const float4 v4 = *(const float4*)(vg + (size_t)(kbase + r) * (3 * HH) + d);
            *(float4*)(Vs + r * 64 + d) = v4;
        }
        if (tid < 64) al[tid] = alg[kbase + tid];
        __syncthreads();

        float s[4][4];
#pragma unroll
        for (int i = 0; i < 4; i++)
#pragma unroll
            for (int j = 0; j < 4; j++) s[i][j] = 0.f;

#pragma unroll 4
        for (int d = 0; d < 64; ++d) {
            float qa[4], kb[4];
#pragma unroll
            for (int i = 0; i < 4; i++) qa[i] = Qs[(ty * 4 + i) * 65 + d];
#pragma unroll
            for (int j = 0; j < 4; j++) kb[j] = Ks[(tx * 4 + j) * 65 + d];
#pragma unroll
            for (int i = 0; i < 4; i++)
#pragma unroll
                for (int j = 0; j < 4; j++) s[i][j] += qa[i] * kb[j];
        }

        const bool diag = (jt == qt);
#pragma unroll
        for (int i = 0; i < 4; i++) {
            const int qr = qbase + ty * 4 + i;
            float lm = -INFINITY;
#pragma unroll
            for (int j = 0; j < 4; j++) {
                const int kc = kbase + tx * 4 + j;
                float sc = s[i][j] * 0.125f + al[tx * 4 + j];
                if (diag && kc > qr) sc = -1e30f;
                s[i][j] = sc;
                lm = fmaxf(lm, sc);
            }
#pragma unroll
            for (int o = 8; o; o >>= 1) lm = fmaxf(lm, __shfl_xor_sync(0xffffffffu, lm, o, 16));
            const float mn = fmaxf(mx[i], lm);
            const float corr = expf(mx[i] - mn);
            mx[i] = mn;
            float rs = 0.f;
#pragma unroll
            for (int j = 0; j < 4; j++) {
                const float p = expf(s[i][j] - mn);
                rs += p;
                Ps[(ty * 4 + i) * 64 + tx * 4 + j] = p;
            }
#pragma unroll
            for (int o = 8; o; o >>= 1) rs += __shfl_xor_sync(0xffffffffu, rs, o, 16);
            lsum[i] = lsum[i] * corr + rs;
#pragma unroll
            for (int j = 0; j < 4; j++) acc[i][j] *= corr;
        }
        __syncthreads();

#pragma unroll 4
        for (int c = 0; c < 64; ++c) {
            const float4 v4 = *(const float4*)(Vs + c * 64 + tx * 4);
#pragma unroll
            for (int i = 0; i < 4; i++) {
                const float p = Ps[(ty * 4 + i) * 64 + c];
                acc[i][0] += p * v4.x; acc[i][1] += p * v4.y;
                acc[i][2] += p * v4.z; acc[i][3] += p * v4.w;
            }
        }
    }

#pragma unroll
    for (int i = 0; i < 4; i++) {
        const float inv = 1.f / lsum[i];
        const float4 o = make_float4(to_tf32(acc[i][0] * inv), to_tf32(acc[i][1] * inv),
                                     to_tf32(acc[i][2] * inv), to_tf32(acc[i][3] * inv));
        *(float4*)(ctx + ((size_t)bb * SS + qbase + ty * 4 + i) * HH + hh * DHH + tx * 4) = o;
    }
}

// ---------------- driver ----------------
extern "C" void kernel_launch(void* const* d_in, const int* in_sizes, int n_in,
                              void* d_out, int out_size) {
    const float* hs    = (const float*)d_in[0];
    const float* alibi = (const float*)d_in[1];
    const float* qkvw  = (const float*)d_in[2];
    const float* qkvb  = (const float*)d_in[3];
    const float* dw    = (const float*)d_in[4];
    const float* db    = (const float*)d_in[5];
    const float* w1    = (const float*)d_in[6];
    const float* b1    = (const float*)d_in[7];
    const float* w2    = (const float*)d_in[8];
    const float* b2    = (const float*)d_in[9];
    const float* l1w   = (const float*)d_in[10];
    const float* l1b   = (const float*)d_in[11];
    const float* l2w   = (const float*)d_in[12];
    const float* l2b   = (const float*)d_in[13];
    float* out = (float*)d_out;

    float *x, *h, *qkv, *ctx, *ff, *wr;
    cudaGetSymbolAddress((void**)&x,   g_x);
    cudaGetSymbolAddress((void**)&h,   g_h);
    cudaGetSymbolAddress((void**)&qkv, g_qkv);
    cudaGetSymbolAddress((void**)&ctx, g_ctx);
    cudaGetSymbolAddress((void**)&ff,  g_ff);
    cudaGetSymbolAddress((void**)&wr,  g_wr);

    cudaFuncSetAttribute(flash_kernel, cudaFuncAttributeMaxDynamicSharedMemorySize, FLASH_SMEM);
    cudaFuncSetAttribute(mma_tn<0>, cudaFuncAttributeMaxDynamicSharedMemorySize, GSMEM);
    cudaFuncSetAttribute(mma_tn<1>, cudaFuncAttributeMaxDynamicSharedMemorySize, GSMEM);
    cudaFuncSetAttribute(mma_tn<2>, cudaFuncAttributeMaxDynamicSharedMemorySize, GSMEM);

    const int n4 = MM * HH / 4;
    copy_kernel<<<(n4 + 255) / 256, 256>>>(hs, x, n4);

    // pre-round all weights to tf32 (scratch g_wr)
    const size_t OFF_QKV = 0, OFF_D = 3145728, OFF_W1 = 4194304, OFF_W2 = 8388608;
    for (int l = 0; l < 2; ++l) {
        const size_t base = (size_t)l * LWF;
        struct { const float* s; size_t n; size_t o; } jobs[4] = {
            { qkvw + (size_t)l * 3 * HH * HH, (size_t)3 * HH * HH, base + OFF_QKV },
            { dw   + (size_t)l * HH * HH,     (size_t)HH * HH,     base + OFF_D   },
            { w1   + (size_t)l * FFD * HH,    (size_t)FFD * HH,    base + OFF_W1  },
            { w2   + (size_t)l * HH * FFD,    (size_t)HH * FFD,    base + OFF_W2  },
        };
        for (int j = 0; j < 4; ++j) {
            const int m4 = (int)(jobs[j].n / 4);
            round_kernel<<<(m4 + 255) / 256, 256>>>(jobs[j].s, wr + jobs[j].o, m4);
        }
    }

    for (int l = 0; l < 2; ++l) {
        const size_t base = (size_t)l * LWF;
        ln_kernel<<<MM, 256>>>(x, l1w + l * HH, l1b + l * HH, h);
        mma_tn<0><<<dim3(3 * HH / 128, MM / 128), 256, GSMEM>>>(
            h, wr + base + OFF_QKV, qkvb + (size_t)l * 3 * HH, nullptr,
            qkv, MM, 3 * HH, HH);
        flash_kernel<<<dim3(SS / 64, NHH, BB), 256, FLASH_SMEM>>>(qkv, alibi, ctx);
        mma_tn<2><<<dim3(HH / 128, MM / 128), 256, GSMEM>>>(
            ctx, wr + base + OFF_D, db + (size_t)l * HH, x,
            x, MM, HH, HH);
        ln_kernel<<<MM, 256>>>(x, l2w + l * HH, l2b + l * HH, h);
        mma_tn<1><<<dim3(FFD / 128, MM / 128), 256, GSMEM>>>(
            h, wr + base + OFF_W1, b1 + (size_t)l * FFD, nullptr,
            ff, MM, FFD, HH);
        mma_tn<2><<<dim3(HH / 128, MM / 128), 256, GSMEM>>>(
            ff, wr + base + OFF_W2, b2 + (size_t)l * HH, x,
            (l == 1) ? out : x, MM, HH, FFD);
    }
}

// round 4
// speedup vs baseline: 2.6313x; 1.3153x over previous
#include <cuda_runtime.h>
#include <math.h>
#include <stdint.h>

// ---------------- problem constants ----------------
#define BB   2
#define SS   2048
#define HH   1024
#define NHH  16
#define DHH  64
#define FFD  4096
#define MM   (BB*SS)     // 4096 rows

// ---------------- scratch (static device globals; no allocation) -----------
__device__ float g_x  [(size_t)MM * HH];        // running residual
__device__ float g_h  [(size_t)MM * HH];        // layernorm output (tf32-rounded)
__device__ float g_qkv[(size_t)MM * 3 * HH];    // qkv projection
__device__ float g_ctx[(size_t)MM * HH];        // attention context (tf32-rounded)
__device__ float g_ff [(size_t)MM * FFD];       // mlp hidden (tf32-rounded)
#define LWF 12582912                             // floats of weights per layer
__device__ float g_wr [(size_t)2 * LWF];        // tf32-rounded weights

// ---------------- small helpers ----------------
__device__ __forceinline__ float warp_sum(float v) {
#pragma unroll
    for (int o = 16; o; o >>= 1) v += __shfl_xor_sync(0xffffffffu, v, o);
    return v;
}
__device__ __forceinline__ float to_tf32(float x) {
    float y;
    asm("cvt.rna.tf32.f32 %0, %1;" : "=f"(y) : "f"(x));
    return y;
}
__device__ __forceinline__ float gelu_exact(float v) {
    return 0.5f * v * (1.0f + erff(v * 0.70710678118654752f));
}
#define MMA_TF32(d, a0, a1, a2, a3, b0, b1)                                   \
    asm volatile("mma.sync.aligned.m16n8k8.row.col.f32.tf32.tf32.f32 "        \
                 "{%0,%1,%2,%3}, {%4,%5,%6,%7}, {%8,%9}, {%0,%1,%2,%3};"      \
                 : "+f"((d)[0]), "+f"((d)[1]), "+f"((d)[2]), "+f"((d)[3])     \
                 : "r"(a0), "r"(a1), "r"(a2), "r"(a3), "r"(b0), "r"(b1))

// ---------------- copy input -> g_x ----------------
__global__ void copy_kernel(const float* __restrict__ in, float* __restrict__ out, int n4) {
    int i = blockIdx.x * blockDim.x + threadIdx.x;
    if (i < n4) ((float4*)out)[i] = ((const float4*)in)[i];
}

// ---------------- tf32 rounding pass (weights) ----------------
__global__ void round_kernel(const float* __restrict__ in, float* __restrict__ out, int n4) {
    int i = blockIdx.x * blockDim.x + threadIdx.x;
    if (i < n4) {
        float4 v = ((const float4*)in)[i];
        v.x = to_tf32(v.x); v.y = to_tf32(v.y); v.z = to_tf32(v.z); v.w = to_tf32(v.w);
        ((float4*)out)[i] = v;
    }
}

// ---------------- layernorm: 1 block (256 thr) per row of 1024 -------------
__global__ void ln_kernel(const float* __restrict__ x, const float* __restrict__ w,
                          const float* __restrict__ b, float* __restrict__ o) {
    __shared__ float r1[8], r2[8];
    const int row = blockIdx.x, tid = threadIdx.x;
    const float4 v = *(const float4*)(x + (size_t)row * HH + tid * 4);
    float s = v.x + v.y + v.z + v.w;
    s = warp_sum(s);
    if ((tid & 31) == 0) r1[tid >> 5] = s;
    __syncthreads();
    float mean = 0.f;
#pragma unroll
    for (int i = 0; i < 8; i++) mean += r1[i];
    mean *= (1.f / (float)HH);
    const float d0 = v.x - mean, d1 = v.y - mean, d2 = v.z - mean, d3 = v.w - mean;
    float sq = d0 * d0 + d1 * d1 + d2 * d2 + d3 * d3;
    sq = warp_sum(sq);
    if ((tid & 31) == 0) r2[tid >> 5] = sq;
    __syncthreads();
    float var = 0.f;
#pragma unroll
    for (int i = 0; i < 8; i++) var += r2[i];
    var *= (1.f / (float)HH);
    const float rstd = rsqrtf(var + 1e-5f);
    const float4 wv = *(const float4*)(w + tid * 4);
    const float4 bv = *(const float4*)(b + tid * 4);
    float4 ov;
    ov.x = to_tf32(d0 * rstd * wv.x + bv.x);
    ov.y = to_tf32(d1 * rstd * wv.y + bv.y);
    ov.z = to_tf32(d2 * rstd * wv.z + bv.z);
    ov.w = to_tf32(d3 * rstd * wv.w + bv.w);
    *(float4*)(o + (size_t)row * HH + tid * 4) = ov;
}

// ---------------- tf32 tensor-core GEMM (TN) -------------------------------
// C[M,N] = A[M,K] * W[N,K]^T + epilogue.  A, W pre-rounded to tf32.
// 128x128x32 CTA tile, 8 warps (2x4), warp tile 64x32, mma.m16n8k8.
#define GSTAGE (2*128*36)
#define GSMEM  (2*GSTAGE*4)

template <int EPI>
__global__ void __launch_bounds__(256, 2) mma_tn(
        const float* __restrict__ A, const float* __restrict__ W,
        const float* __restrict__ bias, const float* __restrict__ res,
        float* __restrict__ C, int M, int N, int K) {
    extern __shared__ float sm[];
    const uint32_t smbase = (uint32_t)__cvta_generic_to_shared(sm);
    const int tid = threadIdx.x;
    const int warp = tid >> 5, lane = tid & 31;
    const int wm = warp >> 2, wn = warp & 3;
    const int g = lane >> 2, t = lane & 3;
    const int mb = blockIdx.y << 7, nb = blockIdx.x << 7;

    const int ra = tid >> 1, ka = (tid & 1) << 4;
    const float* Ag = A + (size_t)(mb + ra) * K + ka;
    const float* Wg = W + (size_t)(nb + ra) * K + ka;
    const uint32_t dA = smbase + (uint32_t)(ra * 36 + ka) * 4u;
    const uint32_t dW = smbase + (uint32_t)(128 * 36 + ra * 36 + ka) * 4u;

    float acc[4][4][4];
#pragma unroll
    for (int a = 0; a < 4; a++)
#pragma unroll
        for (int b = 0; b < 4; b++)
#pragma unroll
            for (int c = 0; c < 4; c++) acc[a][b][c] = 0.f;

    const int nk = K >> 5;
    auto issue = [&](int kt, int s) {
        const float* ap = Ag + (kt << 5);
        const float* wp = Wg + (kt << 5);
        const uint32_t da = dA + (uint32_t)s * (GSTAGE * 4);
        const uint32_t dw = dW + (uint32_t)s * (GSTAGE * 4);
#pragma unroll
        for (int i = 0; i < 4; i++) {
            asm volatile("cp.async.cg.shared.global [%0], [%1], 16;\n"
                         :: "r"(da + i * 16), "l"(ap + i * 4));
            asm volatile("cp.async.cg.shared.global [%0], [%1], 16;\n"
                         :: "r"(dw + i * 16), "l"(wp + i * 4));
        }
        asm volatile("cp.async.commit_group;\n");
    };

    issue(0, 0);
    if (nk > 1) issue(1, 1);

    const uint32_t* su = (const uint32_t*)sm;
    for (int kt = 0; kt < nk; ++kt) {
        if (kt == nk - 1) asm volatile("cp.async.wait_group 0;\n");
        else              asm volatile("cp.async.wait_group 1;\n");
        __syncthreads();
        const uint32_t* as = su + (kt & 1) * GSTAGE;
        const uint32_t* ws = as + 128 * 36;
#pragma unroll
        for (int kk = 0; kk < 4; kk++) {
            const int k = kk * 8;
            uint32_t af[4][4], bf[4][2];
#pragma unroll
            for (int mt = 0; mt < 4; mt++) {
                const int rb = wm * 64 + mt * 16;
                af[mt][0] = as[(rb + g)     * 36 + k + t];
                af[mt][1] = as[(rb + 8 + g) * 36 + k + t];
                af[mt][2] = as[(rb + g)     * 36 + k + t + 4];
                af[mt][3] = as[(rb + 8 + g) * 36 + k + t + 4];
            }
#pragma unroll
            for (int nt = 0; nt < 4; nt++) {
                const int cb = wn * 32 + nt * 8;
                bf[nt][0] = ws[(cb + g) * 36 + k + t];
                bf[nt][1] = ws[(cb + g) * 36 + k + t + 4];
            }
#pragma unroll
            for (int mt = 0; mt < 4; mt++)
#pragma unroll
                for (int nt = 0; nt < 4; nt++)
                    MMA_TF32(acc[mt][nt], af[mt][0], af[mt][1], af[mt][2], af[mt][3],
                             bf[nt][0], bf[nt][1]);
        }
        __syncthreads();
        if (kt + 2 < nk) issue(kt + 2, kt & 1);
    }

#pragma unroll
    for (int mt = 0; mt < 4; mt++) {
        const int r0 = mb + wm * 64 + mt * 16 + g;
#pragma unroll
        for (int nt = 0; nt < 4; nt++) {
            const int cb = nb + wn * 32 + nt * 8 + 2 * t;
            const float b0 = bias[cb], b1 = bias[cb + 1];
#pragma unroll
            for (int hh = 0; hh < 2; hh++) {
                const int rr = r0 + hh * 8;
                float v0 = acc[mt][nt][2 * hh + 0] + b0;
                float v1 = acc[mt][nt][2 * hh + 1] + b1;
                const size_t off = (size_t)rr * N + cb;
                if (EPI == 1) { v0 = to_tf32(gelu_exact(v0)); v1 = to_tf32(gelu_exact(v1)); }
                if (EPI == 2) { const float2 rv = *(const float2*)(res + off); v0 += rv.x; v1 += rv.y; }
                *(float2*)(C + off) = make_float2(v0, v1);
            }
        }
    }
}

// ---------------- tensor-core flash attention (tf32, causal, ALiBi) --------
// grid: (S/128, NH, B), 256 thr (8 warps x 16 q-rows).
// scores_final = alibi[b,h,k] + (q.k)/8  (layer_number cancels)
#define FPAD 68
#define FLASH_SMEM ((128*FPAD + 64*FPAD + 64*FPAD + 128*FPAD + 64) * 4)
__global__ void __launch_bounds__(256, 2) flash_kernel(
        const float* __restrict__ qkv, const float* __restrict__ alibi,
        float* __restrict__ ctx) {
    extern __shared__ float smf[];
    float* Qs = smf;                    // [128][FPAD]
    float* Ks = Qs + 128 * FPAD;        // [64][FPAD]
    float* Vt = Ks + 64 * FPAD;         // [64][FPAD]  (transposed: [dh][key])
    float* Ps = Vt + 64 * FPAD;         // [128][FPAD]
    float* al = Ps + 128 * FPAD;        // [64]
    const uint32_t* Qu = (const uint32_t*)Qs;
    const uint32_t* Ku = (const uint32_t*)Ks;
    const uint32_t* Vu = (const uint32_t*)Vt;
    const uint32_t* Pu = (const uint32_t*)Ps;

    const int qt = blockIdx.x, hh = blockIdx.y, bb = blockIdx.z;
    const int tid = threadIdx.x;
    const int warp = tid >> 5, lane = tid & 31;
    const int g = lane >> 2, t = lane & 3;
    const int wq = warp << 4;           // warp's first q row within tile
    const int qbase = qt << 7;

    const float* qg  = qkv + (size_t)bb * SS * (3 * HH) + hh * DHH;
    const float* kg  = qg + HH;
    const float* vg  = qg + 2 * HH;
    const float* alg = alibi + ((size_t)bb * NHH + hh) * SS;

    // load + tf32-round Q tile (128 rows x 64)
    for (int f = tid; f < 2048; f += 256) {
        const int r = f >> 4, d = (f & 15) << 2;
        const float4 q4 = *(const float4*)(qg + (size_t)(qbase + r) * (3 * HH) + d);
        float* qp = Qs + r * FPAD + d;
        qp[0] = to_tf32(q4.x); qp[1] = to_tf32(q4.y);
        qp[2] = to_tf32(q4.z); qp[3] = to_tf32(q4.w);
    }

    float mx[2] = { -INFINITY, -INFINITY };
    float lsum[2] = { 0.f, 0.f };
    float acc[8][4];
#pragma unroll
    for (int nt = 0; nt < 8; nt++)
#pragma unroll
        for (int c = 0; c < 4; c++) acc[nt][c] = 0.f;

    const int njt = 2 * qt + 2;
    for (int jt = 0; jt < njt; ++jt) {
        const int kbase = jt << 6;
        __syncthreads();
        // load K (rounded) + V (rounded, transposed)
        for (int f = tid; f < 1024; f += 256) {
            const int r = f >> 4, d = (f & 15) << 2;
            const float4 k4 = *(const float4*)(kg + (size_t)(kbase + r) * (3 * HH) + d);
            float* kp = Ks + r * FPAD + d;
            kp[0] = to_tf32(k4.x); kp[1] = to_tf32(k4.y);
            kp[2] = to_tf32(k4.z); kp[3] = to_tf32(k4.w);
            const float4 v4 = *(const float4*)(vg + (size_t)(kbase + r) * (3 * HH) + d);
            Vt[(d + 0) * FPAD + r] = to_tf32(v4.x);
            Vt[(d + 1) * FPAD + r] = to_tf32(v4.y);
            Vt[(d + 2) * FPAD + r] = to_tf32(v4.z);
            Vt[(d + 3) * FPAD + r] = to_tf32(v4.w);
        }
        if (tid < 64) al[tid] = alg[kbase + tid];
        __syncthreads();

        // ---- S = Q K^T (m16 x n64 per warp) ----
        float s[8][4];
#pragma unroll
        for (int nt = 0; nt < 8; nt++)
#pragma unroll
            for (int c = 0; c < 4; c++) s[nt][c] = 0.f;
#pragma unroll
        for (int kk = 0; kk < 8; ++kk) {
            const int k = kk << 3;
            const uint32_t a0 = Qu[(wq + g)     * FPAD + k + t];
            const uint32_t a1 = Qu[(wq + 8 + g) * FPAD + k + t];
            const uint32_t a2 = Qu[(wq + g)     * FPAD + k + t + 4];
            const uint32_t a3 = Qu[(wq + 8 + g) * FPAD + k + t + 4];
#pragma unroll
            for (int nt = 0; nt < 8; ++nt) {
                const uint32_t b0 = Ku[(nt * 8 + g) * FPAD + k + t];
                const uint32_t b1 = Ku[(nt * 8 + g) * FPAD + k + t + 4];
                MMA_TF32(s[nt], a0, a1, a2, a3, b0, b1);
            }
        }

        // ---- online softmax (per thread: 2 rows x 16 cols) ----
        const bool need_mask = (jt >= 2 * qt);
#pragma unroll
        for (int r = 0; r < 2; ++r) {
            const int qr = qbase + wq + g + r * 8;
            float rowmax = -INFINITY;
#pragma unroll
            for (int nt = 0; nt < 8; ++nt) {
#pragma unroll
                for (int c = 0; c < 2; ++c) {
                    const int col = nt * 8 + 2 * t + c;
                    float v = s[nt][r * 2 + c] * 0.125f + al[col];
                    if (need_mask && (kbase + col > qr)) v = -1e30f;
                    s[nt][r * 2 + c] = v;
                    rowmax = fmaxf(rowmax, v);
                }
            }
            rowmax = fmaxf(rowmax, __shfl_xor_sync(0xffffffffu, rowmax, 1));
            rowmax = fmaxf(rowmax, __shfl_xor_sync(0xffffffffu, rowmax, 2));
            const float mn = fmaxf(mx[r], rowmax);
            const float corr = __expf(mx[r] - mn);
            mx[r] = mn;
            float rs = 0.f;
#pragma unroll
            for (int nt = 0; nt < 8; ++nt) {
                const float p0 = to_tf32(__expf(s[nt][r * 2 + 0] - mn));
                const float p1 = to_tf32(__expf(s[nt][r * 2 + 1] - mn));
                rs += p0 + p1;
                *(float2*)(Ps + (wq + r * 8 + g) * FPAD + nt * 8 + 2 * t) =
                    make_float2(p0, p1);
            }
            rs += __shfl_xor_sync(0xffffffffu, rs, 1);
            rs += __shfl_xor_sync(0xffffffffu, rs, 2);
            lsum[r] = lsum[r] * corr + rs;
#pragma unroll
            for (int nt = 0; nt < 8; ++nt) {
                acc[nt][r * 2 + 0] *= corr;
                acc[nt][r * 2 + 1] *= corr;
            }
        }
        __syncwarp();

        // ---- O += P V (m16 x n64 per warp, k = 64 keys) ----
#pragma unroll
        for (int kk = 0; kk < 8; ++kk) {
            const int k = kk << 3;
            const uint32_t a0 = Pu[(wq + g)     * FPAD + k + t];
            const uint32_t a1 = Pu[(wq + 8 + g) * FPAD + k + t];
            const uint32_t a2 = Pu[(wq + g)     * FPAD + k + t + 4];
            const uint32_t a3 = Pu[(wq + 8 + g) * FPAD + k + t + 4];
#pragma unroll
            for (int nt = 0; nt < 8; ++nt) {
                const uint32_t b0 = Vu[(nt * 8 + g) * FPAD + k + t];
                const uint32_t b1 = Vu[(nt * 8 + g) * FPAD + k + t + 4];
                MMA_TF32(acc[nt], a0, a1, a2, a3, b0, b1);
            }
        }
    }

    // ---- write ctx (tf32-rounded; feeds dense GEMM) ----
    const float inv0 = 1.f / lsum[0], inv1 = 1.f / lsum[1];
    const int r0 = qbase + wq + g;
    float* o0 = ctx + ((size_t)bb * SS + r0) * HH + hh * DHH;
    float* o1 = o0 + (size_t)8 * HH;
#pragma unroll
    for (int nt = 0; nt < 8; ++nt) {
        const int col = nt * 8 + 2 * t;
        *(float2*)(o0 + col) = make_float2(to_tf32(acc[nt][0] * inv0),
                                           to_tf32(acc[nt][1] * inv0));
        *(float2*)(o1 + col) = make_float2(to_tf32(acc[nt][2] * inv1),
                                           to_tf32(acc[nt][3] * inv1));
    }
}

// ---------------- driver ----------------
extern "C" void kernel_launch(void* const* d_in, const int* in_sizes, int n_in,
                              void* d_out, int out_size) {
    const float* hs    = (const float*)d_in[0];
    const float* alibi = (const float*)d_in[1];
    const float* qkvw  = (const float*)d_in[2];
    const float* qkvb  = (const float*)d_in[3];
    const float* dw    = (const float*)d_in[4];
    const float* db    = (const float*)d_in[5];
    const float* w1    = (const float*)d_in[6];
    const float* b1    = (const float*)d_in[7];
    const float* w2    = (const float*)d_in[8];
    const float* b2    = (const float*)d_in[9];
    const float* l1w   = (const float*)d_in[10];
    const float* l1b   = (const float*)d_in[11];
    const float* l2w   = (const float*)d_in[12];
    const float* l2b   = (const float*)d_in[13];
    float* out = (float*)d_out;

    float *x, *h, *qkv, *ctx, *ff, *wr;
    cudaGetSymbolAddress((void**)&x,   g_x);
    cudaGetSymbolAddress((void**)&h,   g_h);
    cudaGetSymbolAddress((void**)&qkv, g_qkv);
    cudaGetSymbolAddress((void**)&ctx, g_ctx);
    cudaGetSymbolAddress((void**)&ff,  g_ff);
    cudaGetSymbolAddress((void**)&wr,  g_wr);

    cudaFuncSetAttribute(flash_kernel, cudaFuncAttributeMaxDynamicSharedMemorySize, FLASH_SMEM);
    cudaFuncSetAttribute(mma_tn<0>, cudaFuncAttributeMaxDynamicSharedMemorySize, GSMEM);
    cudaFuncSetAttribute(mma_tn<1>, cudaFuncAttributeMaxDynamicSharedMemorySize, GSMEM);
    cudaFuncSetAttribute(mma_tn<2>, cudaFuncAttributeMaxDynamicSharedMemorySize, GSMEM);

    const int n4 = MM * HH / 4;
    copy_kernel<<<(n4 + 255) / 256, 256>>>(hs, x, n4);

    // pre-round all weights to tf32 (scratch g_wr)
    const size_t OFF_QKV = 0, OFF_D = 3145728, OFF_W1 = 4194304, OFF_W2 = 8388608;
    for (int l = 0; l < 2; ++l) {
        const size_t base = (size_t)l * LWF;
        struct { const float* s; size_t n; size_t o; } jobs[4] = {
            { qkvw + (size_t)l * 3 * HH * HH, (size_t)3 * HH * HH, base + OFF_QKV },
            { dw   + (size_t)l * HH * HH,     (size_t)HH * HH,     base + OFF_D   },
            { w1   + (size_t)l * FFD * HH,    (size_t)FFD * HH,    base + OFF_W1  },
            { w2   + (size_t)l * HH * FFD,    (size_t)HH * FFD,    base + OFF_W2  },
        };
        for (int j = 0; j < 4; ++j) {
            const int m4 = (int)(jobs[j].n / 4);
            round_kernel<<<(m4 + 255) / 256, 256>>>(jobs[j].s, wr + jobs[j].o, m4);
        }
    }

    for (int l = 0; l < 2; ++l) {
        const size_t base = (size_t)l * LWF;
        ln_kernel<<<MM, 256>>>(x, l1w + l * HH, l1b + l * HH, h);
        mma_tn<0><<<dim3(3 * HH / 128, MM / 128), 256, GSMEM>>>(
            h, wr + base + OFF_QKV, qkvb + (size_t)l * 3 * HH, nullptr,
            qkv, MM, 3 * HH, HH);
        flash_kernel<<<dim3(SS / 128, NHH, BB), 256, FLASH_SMEM>>>(qkv, alibi, ctx);
        mma_tn<2><<<dim3(HH / 128, MM / 128), 256, GSMEM>>>(
            ctx, wr + base + OFF_D, db + (size_t)l * HH, x,
            x, MM, HH, HH);
        ln_kernel<<<MM, 256>>>(x, l2w + l * HH, l2b + l * HH, h);
        mma_tn<1><<<dim3(FFD / 128, MM / 128), 256, GSMEM>>>(
            h, wr + base + OFF_W1, b1 + (size_t)l * FFD, nullptr,
            ff, MM, FFD, HH);
        mma_tn<2><<<dim3(HH / 128, MM / 128), 256, GSMEM>>>(
            ff, wr + base + OFF_W2, b2 + (size_t)l * HH, x,
            (l == 1) ? out : x, MM, HH, FFD);
    }
}

// round 6
// speedup vs baseline: 3.0475x; 1.1582x over previous
#include <cuda_runtime.h>
#include <cuda_bf16.h>
#include <math.h>
#include <stdint.h>

// ---------------- problem constants ----------------
#define BB   2
#define SS   2048
#define HH   1024
#define NHH  16
#define DHH  64
#define FFD  4096
#define MM   (BB*SS)     // 4096 rows

// ---------------- scratch (static device globals; no allocation) -----------
__device__ float          g_x  [(size_t)MM * HH];      // running residual (fp32)
__device__ __nv_bfloat16  g_h  [(size_t)MM * HH];      // layernorm output
__device__ __nv_bfloat16  g_qkv[(size_t)MM * 3 * HH];  // qkv projection
__device__ __nv_bfloat16  g_ctx[(size_t)MM * HH];      // attention context
__device__ __nv_bfloat16  g_ff [(size_t)MM * FFD];     // mlp hidden
#define LWF 12582912                                   // weight elems per layer
__device__ __nv_bfloat16  g_wr [(size_t)2 * LWF];      // bf16 weights

// ---------------- small helpers ----------------
__device__ __forceinline__ float warp_sum(float v) {
#pragma unroll
    for (int o = 16; o; o >>= 1) v += __shfl_xor_sync(0xffffffffu, v, o);
    return v;
}
__device__ __forceinline__ float gelu_exact(float v) {
    return 0.5f * v * (1.0f + erff(v * 0.70710678118654752f));
}
// m16n8k16 row.col bf16 -> f32
#define MMA_BF16(d, a0, a1, a2, a3, b0, b1)                                   \
    asm volatile("mma.sync.aligned.m16n8k16.row.col.f32.bf16.bf16.f32 "       \
                 "{%0,%1,%2,%3}, {%4,%5,%6,%7}, {%8,%9}, {%0,%1,%2,%3};"      \
                 : "+f"((d)[0]), "+f"((d)[1]), "+f"((d)[2]), "+f"((d)[3])     \
                 : "r"(a0), "r"(a1), "r"(a2), "r"(a3), "r"(b0), "r"(b1))

// ---------------- copy input -> g_x ----------------
__global__ void copy_kernel(const float* __restrict__ in, float* __restrict__ out, int n4) {
    int i = blockIdx.x * blockDim.x + threadIdx.x;
    if (i < n4) ((float4*)out)[i] = ((const float4*)in)[i];
}

// ---------------- fp32 -> bf16 weight conversion ----------------
__global__ void cvt_kernel(const float* __restrict__ in, __nv_bfloat16* __restrict__ out, int n4) {
    int i = blockIdx.x * blockDim.x + threadIdx.x;
    if (i < n4) {
        const float4 v = ((const float4*)in)[i];
        __nv_bfloat162 a = __floats2bfloat162_rn(v.x, v.y);
        __nv_bfloat162 b = __floats2bfloat162_rn(v.z, v.w);
        uint2 w; w.x = *(uint32_t*)&a; w.y = *(uint32_t*)&b;
        ((uint2*)out)[i] = w;
    }
}

// ---------------- layernorm: 1 block (256 thr) per row of 1024 -------------
// fp32 in, bf16 out (feeds tensor-core GEMMs only).
__global__ void ln_kernel(const float* __restrict__ x, const float* __restrict__ w,
                          const float* __restrict__ b, __nv_bfloat16* __restrict__ o) {
    __shared__ float r1[8], r2[8];
    const int row = blockIdx.x, tid = threadIdx.x;
    const float4 v = *(const float4*)(x + (size_t)row * HH + tid * 4);
    float s = v.x + v.y + v.z + v.w;
    s = warp_sum(s);
    if ((tid & 31) == 0) r1[tid >> 5] = s;
    __syncthreads();
    float mean = 0.f;
#pragma unroll
    for (int i = 0; i < 8; i++) mean += r1[i];
    mean *= (1.f / (float)HH);
    const float d0 = v.x - mean, d1 = v.y - mean, d2 = v.z - mean, d3 = v.w - mean;
    float sq = d0 * d0 + d1 * d1 + d2 * d2 + d3 * d3;
    sq = warp_sum(sq);
    if ((tid & 31) == 0) r2[tid >> 5] = sq;
    __syncthreads();
    float var = 0.f;
#pragma unroll
    for (int i = 0; i < 8; i++) var += r2[i];
    var *= (1.f / (float)HH);
    const float rstd = rsqrtf(var + 1e-5f);
    const float4 wv = *(const float4*)(w + tid * 4);
    const float4 bv = *(const float4*)(b + tid * 4);
    __nv_bfloat162 o0 = __floats2bfloat162_rn(d0 * rstd * wv.x + bv.x, d1 * rstd * wv.y + bv.y);
    __nv_bfloat162 o1 = __floats2bfloat162_rn(d2 * rstd * wv.z + bv.z, d3 * rstd * wv.w + bv.w);
    uint2 pk; pk.x = *(uint32_t*)&o0; pk.y = *(uint32_t*)&o1;
    *(uint2*)(o + (size_t)row * HH + tid * 4) = pk;
}

// ---------------- bf16 tensor-core GEMM (TN) -------------------------------
// C[M,N] = A[M,K] * W[N,K]^T + epilogue.  A, W bf16, accum fp32.
// 128x128x64 CTA tile, 8 warps (2x4), warp tile 64x32, mma.m16n8k16.
// EPI 0: bf16(+bias)   EPI 1: bf16(gelu(+bias))   EPI 2: fp32 +bias +res
#define GSTRIDE 36                       // 32-bit words per 64-bf16 row (+8 pad)
#define GSTAGE  (2*128*GSTRIDE)          // words per stage (A tile + W tile)
#define GSMEM   (2*GSTAGE*4)             // bytes (2 stages) = 73728

template <int EPI>
__global__ void __launch_bounds__(256, 2) mma_tn(
        const __nv_bfloat16* __restrict__ A, const __nv_bfloat16* __restrict__ W,
        const float* __restrict__ bias, const float* __restrict__ res,
        void* __restrict__ Cout, int M, int N, int K) {
    extern __shared__ uint32_t sm[];
    const uint32_t smbase = (uint32_t)__cvta_generic_to_shared(sm);
    const int tid = threadIdx.x;
    const int warp = tid >> 5, lane = tid & 31;
    const int wm = warp >> 2, wn = warp & 3;
    const int g = lane >> 2, t = lane & 3;
    const int mb = blockIdx.y << 7, nb = blockIdx.x << 7;

    // staging: thread -> row ra, bf16 col offset ka (0 or 32), 4 x 16B chunks
    const int ra = tid >> 1, ka = (tid & 1) << 5;
    const __nv_bfloat16* Ag = A + (size_t)(mb + ra) * K + ka;
    const __nv_bfloat16* Wg = W + (size_t)(nb + ra) * K + ka;
    const uint32_t dA = smbase + (uint32_t)(ra * 144 + ka * 2);
    const uint32_t dW = dA + 128 * 144;

    float acc[4][4][4];
#pragma unroll
    for (int a = 0; a < 4; a++)
#pragma unroll
        for (int b = 0; b < 4; b++)
#pragma unroll
            for (int c = 0; c < 4; c++) acc[a][b][c] = 0.f;

    const int nk = K >> 6;
    auto issue = [&](int kt, int s) {
        const __nv_bfloat16* ap = Ag + (kt << 6);
        const __nv_bfloat16* wp = Wg + (kt << 6);
        const uint32_t da = dA + (uint32_t)s * (GSTAGE * 4);
        const uint32_t dw = dW + (uint32_t)s * (GSTAGE * 4);
#pragma unroll
        for (int i = 0; i < 4; i++) {
            asm volatile("cp.async.cg.shared.global [%0], [%1], 16;\n"
                         :: "r"(da + i * 16), "l"(ap + i * 8));
            asm volatile("cp.async.cg.shared.global [%0], [%1], 16;\n"
                         :: "r"(dw + i * 16), "l"(wp + i * 8));
        }
        asm volatile("cp.async.commit_group;\n");
    };

    issue(0, 0);
    if (nk > 1) issue(1, 1);

    for (int kt = 0; kt < nk; ++kt) {
        if (kt == nk - 1) asm volatile("cp.async.wait_group 0;\n");
        else              asm volatile("cp.async.wait_group 1;\n");
        __syncthreads();
        const uint32_t* as = sm + (kt & 1) * GSTAGE;
        const uint32_t* ws = as + 128 * GSTRIDE;
#pragma unroll
        for (int kk = 0; kk < 4; kk++) {
            const int k = kk << 3;                 // word offset (16 bf16 per step)
            uint32_t af[4][4], bf[4][2];
#pragma unroll
            for (int mt = 0; mt < 4; mt++) {
                const int rb = wm * 64 + mt * 16;
                af[mt][0] = as[(rb + g)     * GSTRIDE + k + t];
                af[mt][1] = as[(rb + 8 + g) * GSTRIDE + k + t];
                af[mt][2] = as[(rb + g)     * GSTRIDE + k + t + 4];
                af[mt][3] = as[(rb + 8 + g) * GSTRIDE + k + t + 4];
            }
#pragma unroll
            for (int nt = 0; nt < 4; nt++) {
                const int cb = wn * 32 + nt * 8;
                bf[nt][0] = ws[(cb + g) * GSTRIDE + k + t];
                bf[nt][1] = ws[(cb + g) * GSTRIDE + k + t + 4];
            }
#pragma unroll
            for (int mt = 0; mt < 4; mt++)
#pragma unroll
                for (int nt = 0; nt < 4; nt++)
                    MMA_BF16(acc[mt][nt], af[mt][0], af[mt][1], af[mt][2], af[mt][3],
                             bf[nt][0], bf[nt][1]);
        }
        __syncthreads();
        if (kt + 2 < nk) issue(kt + 2, kt & 1);
    }

    // epilogue: c0,c1 -> (row g, cols 2t,2t+1); c2,c3 -> (row g+8)
#pragma unroll
    for (int mt = 0; mt < 4; mt++) {
        const int r0 = mb + wm * 64 + mt * 16 + g;
#pragma unroll
        for (int nt = 0; nt < 4; nt++) {
            const int cb = nb + wn * 32 + nt * 8 + 2 * t;
            const float b0 = bias[cb], b1 = bias[cb + 1];
#pragma unroll
            for (int hh = 0; hh < 2; hh++) {
                const int rr = r0 + hh * 8;
                float v0 = acc[mt][nt][2 * hh + 0] + b0;
                float v1 = acc[mt][nt][2 * hh + 1] + b1;
                const size_t off = (size_t)rr * N + cb;
                if (EPI == 2) {
                    const float2 rv = *(const float2*)(res + off);
                    *(float2*)((float*)Cout + off) = make_float2(v0 + rv.x, v1 + rv.y);
                } else {
                    if (EPI == 1) { v0 = gelu_exact(v0); v1 = gelu_exact(v1); }
                    __nv_bfloat162 h2 = __floats2bfloat162_rn(v0, v1);
                    *(uint32_t*)((__nv_bfloat16*)Cout + off) = *(uint32_t*)&h2;
                }
            }
        }
    }
}

// ---------------- bf16 tensor-core flash attention (causal, ALiBi) ---------
// grid: (S/128, NH, B), 256 thr (8 warps x 16 q-rows).
// scores_final = alibi[b,h,k] + (q.k)/8  (layer_number cancels)
#define FSTR 36                                        // words per row
#define FLASH_SMEM ((128*FSTR + 64*FSTR + 64*FSTR + 128*FSTR + 64) * 4)
__global__ void __launch_bounds__(256, 2) flash_kernel(
        const __nv_bfloat16* __restrict__ qkv, const float* __restrict__ alibi,
        __nv_bfloat16* __restrict__ ctx) {
    extern __shared__ uint32_t smw[];
    uint32_t* Qs = smw;                    // [128][FSTR]  (q rows, 64 bf16)
    uint32_t* Ks = Qs + 128 * FSTR;        // [64][FSTR]
    uint32_t* Vt = Ks + 64 * FSTR;         // [64][FSTR]   (transposed: [dh][key])
    uint32_t* Ps = Vt + 64 * FSTR;         // [128][FSTR]
    float*    al = (float*)(Ps + 128 * FSTR);   // [64]
    __nv_bfloat16* Vtb = (__nv_bfloat16*)Vt;

    const int qt = blockIdx.x, hh = blockIdx.y, bb = blockIdx.z;
    const int tid = threadIdx.x;
    const int warp = tid >> 5, lane = tid & 31;
    const int g = lane >> 2, t = lane & 3;
    const int wq = warp << 4;
    const int qbase = qt << 7;

    const __nv_bfloat16* qg  = qkv + (size_t)bb * SS * (3 * HH) + hh * DHH;
    const __nv_bfloat16* kg  = qg + HH;
    const __nv_bfloat16* vg  = qg + 2 * HH;
    const float* alg = alibi + ((size_t)bb * NHH + hh) * SS;

    // load Q tile (128 rows x 64 bf16): 1024 16B chunks
    for (int f = tid; f < 1024; f += 256) {
        const int r = f >> 3, c = (f & 7) << 3;          // c: bf16 offset
        const uint4 q4 = *(const uint4*)(qg + (size_t)(qbase + r) * (3 * HH) + c);
        *(uint4*)(Qs + r * FSTR + (c >> 1)) = q4;
    }

    float mx[2] = { -INFINITY, -INFINITY };
    float lsum[2] = { 0.f, 0.f };
    float acc[8][4];
#pragma unroll
    for (int nt = 0; nt < 8; nt++)
#pragma unroll
        for (int c = 0; c < 4; c++) acc[nt][c] = 0.f;

    const int njt = 2 * qt + 2;
    for (int jt = 0; jt < njt; ++jt) {
        const int kbase = jt << 6;
        __syncthreads();
        // K: direct copy; V: transpose to [dh][key]
        for (int f = tid; f < 512; f += 256) {
            const int r = f >> 3, c = (f & 7) << 3;
            const uint4 k4 = *(const uint4*)(kg + (size_t)(kbase + r) * (3 * HH) + c);
            *(uint4*)(Ks + r * FSTR + (c >> 1)) = k4;
            const uint4 v4 = *(const uint4*)(vg + (size_t)(kbase + r) * (3 * HH) + c);
            const __nv_bfloat16* ve = (const __nv_bfloat16*)&v4;
#pragma unroll
            for (int j = 0; j < 8; j++) Vtb[(c + j) * (2 * FSTR) + r] = ve[j];
        }
        if (tid < 64) al[tid] = alg[kbase + tid];
        __syncthreads();

        // ---- S = Q K^T (m16 x n64 per warp, k=64 via 4 x k16) ----
        float s[8][4];
#pragma unroll
        for (int nt = 0; nt < 8; nt++)
#pragma unroll
            for (int c = 0; c < 4; c++) s[nt][c] = 0.f;
#pragma unroll
        for (int kk = 0; kk < 4; ++kk) {
            const int k = kk << 3;
            const uint32_t a0 = Qs[(wq + g)     * FSTR + k + t];
            const uint32_t a1 = Qs[(wq + 8 + g) * FSTR + k + t];
            const uint32_t a2 = Qs[(wq + g)     * FSTR + k + t + 4];
            const uint32_t a3 = Qs[(wq + 8 + g) * FSTR + k + t + 4];
#pragma unroll
            for (int nt = 0; nt < 8; ++nt) {
                const uint32_t b0 = Ks[(nt * 8 + g) * FSTR + k + t];
                const uint32_t b1 = Ks[(nt * 8 + g) * FSTR + k + t + 4];
                MMA_BF16(s[nt], a0, a1, a2, a3, b0, b1);
            }
        }

        // ---- online softmax (per thread: 2 rows x 16 cols) ----
        const bool need_mask = (jt >= 2 * qt);
#pragma unroll
        for (int r = 0; r < 2; ++r) {
            const int qr = qbase + wq + g + r * 8;
            float rowmax = -INFINITY;
#pragma unroll
            for (int nt = 0; nt < 8; ++nt) {
#pragma unroll
                for (int c = 0; c < 2; ++c) {
                    const int col = nt * 8 + 2 * t + c;
                    float v = s[nt][r * 2 + c] * 0.125f + al[col];
                    if (need_mask && (kbase + col > qr)) v = -1e30f;
                    s[nt][r * 2 + c] = v;
                    rowmax = fmaxf(rowmax, v);
                }
            }
            rowmax = fmaxf(rowmax, __shfl_xor_sync(0xffffffffu, rowmax, 1));
            rowmax = fmaxf(rowmax, __shfl_xor_sync(0xffffffffu, rowmax, 2));
            const float mn = fmaxf(mx[r], rowmax);
            const float corr = __expf(mx[r] - mn);
            mx[r] = mn;
            float rs = 0.f;
#pragma unroll
            for (int nt = 0; nt < 8; ++nt) {
                const float p0 = __expf(s[nt][r * 2 + 0] - mn);
                const float p1 = __expf(s[nt][r * 2 + 1] - mn);
                const __nv_bfloat162 h2 = __floats2bfloat162_rn(p0, p1);
                rs += __bfloat162float(h2.x) + __bfloat162float(h2.y);
                Ps[(wq + r * 8 + g) * FSTR + nt * 4 + t] = *(const uint32_t*)&h2;
            }
            rs += __shfl_xor_sync(0xffffffffu, rs, 1);
            rs += __shfl_xor_sync(0xffffffffu, rs, 2);
            lsum[r] = lsum[r] * corr + rs;
#pragma unroll
            for (int nt = 0; nt < 8; ++nt) {
                acc[nt][r * 2 + 0] *= corr;
                acc[nt][r * 2 + 1] *= corr;
            }
        }
        __syncwarp();

        // ---- O += P V (m16 x n64 per warp, k = 64 keys via 4 x k16) ----
#pragma unroll
        for (int kk = 0; kk < 4; ++kk) {
            const int k = kk << 3;
            const uint32_t a0 = Ps[(wq + g)     * FSTR + k + t];
            const uint32_t a1 = Ps[(wq + 8 + g) * FSTR + k + t];
            const uint32_t a2 = Ps[(wq + g)     * FSTR + k + t + 4];
            const uint32_t a3 = Ps[(wq + 8 + g) * FSTR + k + t + 4];
#pragma unroll
            for (int nt = 0; nt < 8; ++nt) {
                const uint32_t b0 = Vt[(nt * 8 + g) * FSTR + k + t];
                const uint32_t b1 = Vt[(nt * 8 + g) * FSTR + k + t + 4];
                MMA_BF16(acc[nt], a0, a1, a2, a3, b0, b1);
            }
        }
    }

    // ---- write ctx (bf16; feeds dense GEMM) ----
    const float inv0 = 1.f / lsum[0], inv1 = 1.f / lsum[1];
    const int r0 = qbase + wq + g;
    __nv_bfloat16* o0 = ctx + ((size_t)bb * SS + r0) * HH + hh * DHH;
    __nv_bfloat16* o1 = o0 + (size_t)8 * HH;
#pragma unroll
    for (int nt = 0; nt < 8; ++nt) {
        const int col = nt * 8 + 2 * t;
        __nv_bfloat162 w0 = __floats2bfloat162_rn(acc[nt][0] * inv0, acc[nt][1] * inv0);
        __nv_bfloat162 w1 = __floats2bfloat162_rn(acc[nt][2] * inv1, acc[nt][3] * inv1);
        *(uint32_t*)(o0 + col) = *(uint32_t*)&w0;
        *(uint32_t*)(o1 + col) = *(uint32_t*)&w1;
    }
}

// ---------------- driver ----------------
extern "C" void kernel_launch(void* const* d_in, const int* in_sizes, int n_in,
                              void* d_out, int out_size) {
    const float* hs    = (const float*)d_in[0];
    const float* alibi = (const float*)d_in[1];
    const float* qkvw  = (const float*)d_in[2];
    const float* qkvb  = (const float*)d_in[3];
    const float* dw    = (const float*)d_in[4];
    const float* db    = (const float*)d_in[5];
    const float* w1    = (const float*)d_in[6];
    const float* b1    = (const float*)d_in[7];
    const float* w2    = (const float*)d_in[8];
    const float* b2    = (const float*)d_in[9];
    const float* l1w   = (const float*)d_in[10];
    const float* l1b   = (const float*)d_in[11];
    const float* l2w   = (const float*)d_in[12];
    const float* l2b   = (const float*)d_in[13];
    float* out = (float*)d_out;

    float *x;
    __nv_bfloat16 *h, *qkv, *ctx, *ff, *wr;
    cudaGetSymbolAddress((void**)&x,   g_x);
    cudaGetSymbolAddress((void**)&h,   g_h);
    cudaGetSymbolAddress((void**)&qkv, g_qkv);
    cudaGetSymbolAddress((void**)&ctx, g_ctx);
    cudaGetSymbolAddress((void**)&ff,  g_ff);
    cudaGetSymbolAddress((void**)&wr,  g_wr);

    cudaFuncSetAttribute(flash_kernel, cudaFuncAttributeMaxDynamicSharedMemorySize, FLASH_SMEM);
    cudaFuncSetAttribute(mma_tn<0>, cudaFuncAttributeMaxDynamicSharedMemorySize, GSMEM);
    cudaFuncSetAttribute(mma_tn<1>, cudaFuncAttributeMaxDynamicSharedMemorySize, GSMEM);
    cudaFuncSetAttribute(mma_tn<2>, cudaFuncAttributeMaxDynamicSharedMemorySize, GSMEM);

    const int n4 = MM * HH / 4;
    copy_kernel<<<(n4 + 255) / 256, 256>>>(hs, x, n4);

    // convert all weights to bf16 once (scratch g_wr)
    const size_t OFF_QKV = 0, OFF_D = 3145728, OFF_W1 = 4194304, OFF_W2 = 8388608;
    for (int l = 0; l < 2; ++l) {
        const size_t base = (size_t)l * LWF;
        struct { const float* s; size_t n; size_t o; } jobs[4] = {
            { qkvw + (size_t)l * 3 * HH * HH, (size_t)3 * HH * HH, base + OFF_QKV },
            { dw   + (size_t)l * HH * HH,     (size_t)HH * HH,     base + OFF_D   },
            { w1   + (size_t)l * FFD * HH,    (size_t)FFD * HH,    base + OFF_W1  },
            { w2   + (size_t)l * HH * FFD,    (size_t)HH * FFD,    base + OFF_W2  },
        };
        for (int j = 0; j < 4; ++j) {
            const int m4 = (int)(jobs[j].n / 4);
            cvt_kernel<<<(m4 + 255) / 256, 256>>>(jobs[j].s, wr + jobs[j].o, m4);
        }
    }

    for (int l = 0; l < 2; ++l) {
        const size_t base = (size_t)l * LWF;
        ln_kernel<<<MM, 256>>>(x, l1w + l * HH, l1b + l * HH, h);
        mma_tn<0><<<dim3(3 * HH / 128, MM / 128), 256, GSMEM>>>(
            h, wr + base + OFF_QKV, qkvb + (size_t)l * 3 * HH, nullptr,
            qkv, MM, 3 * HH, HH);
        flash_kernel<<<dim3(SS / 128, NHH, BB), 256, FLASH_SMEM>>>(qkv, alibi, ctx);
        mma_tn<2><<<dim3(HH / 128, MM / 128), 256, GSMEM>>>(
            ctx, wr + base + OFF_D, db + (size_t)l * HH, x,
            x, MM, HH, HH);
        ln_kernel<<<MM, 256>>>(x, l2w + l * HH, l2b + l * HH, h);
        mma_tn<1><<<dim3(FFD / 128, MM / 128), 256, GSMEM>>>(
            h, wr + base + OFF_W1, b1 + (size_t)l * FFD, nullptr,
            ff, MM, FFD, HH);
        mma_tn<2><<<dim3(HH / 128, MM / 128), 256, GSMEM>>>(
            ff, wr + base + OFF_W2, b2 + (size_t)l * HH, x,
            (l == 1) ? out : x, MM, HH, FFD);
    }
}

// round 9
// speedup vs baseline: 6.4242x; 2.1081x over previous
#include <cuda_runtime.h>
#include <cuda_bf16.h>
#include <math.h>
#include <stdint.h>

// ---------------- problem constants ----------------
#define BB   2
#define SS   2048
#define HH   1024
#define NHH  16
#define DHH  64
#define FFD  4096
#define MM   (BB*SS)     // 4096 rows

// ---------------- scratch (static device globals; no allocation) -----------
__device__ float          g_x  [(size_t)MM * HH];      // running residual (fp32)
__device__ __nv_bfloat16  g_h  [(size_t)MM * HH];      // layernorm output
__device__ __nv_bfloat16  g_qkv[(size_t)MM * 3 * HH];  // qkv projection
__device__ __nv_bfloat16  g_ctx[(size_t)MM * HH];      // attention context
__device__ __nv_bfloat16  g_ff [(size_t)MM * FFD];     // mlp hidden
#define LWF 12582912                                   // weight elems per layer
__device__ __nv_bfloat16  g_wr [(size_t)2 * LWF];      // bf16 weights

// ---------------- small helpers ----------------
__device__ __forceinline__ float warp_sum(float v) {
#pragma unroll
    for (int o = 16; o; o >>= 1) v += __shfl_xor_sync(0xffffffffu, v, o);
    return v;
}
__device__ __forceinline__ float gelu_exact(float v) {
    return 0.5f * v * (1.0f + erff(v * 0.70710678118654752f));
}
#define MMA_BF16(d, a0, a1, a2, a3, b0, b1)                                   \
    asm volatile("mma.sync.aligned.m16n8k16.row.col.f32.bf16.bf16.f32 "       \
                 "{%0,%1,%2,%3}, {%4,%5,%6,%7}, {%8,%9}, {%0,%1,%2,%3};"      \
                 : "+f"((d)[0]), "+f"((d)[1]), "+f"((d)[2]), "+f"((d)[3])     \
                 : "r"(a0), "r"(a1), "r"(a2), "r"(a3), "r"(b0), "r"(b1))

__device__ __forceinline__ void ldsm_x4(uint32_t* r, uint32_t a) {
    asm volatile("ldmatrix.sync.aligned.m8n8.x4.shared.b16 {%0,%1,%2,%3}, [%4];"
                 : "=r"(r[0]), "=r"(r[1]), "=r"(r[2]), "=r"(r[3]) : "r"(a));
}
__device__ __forceinline__ void ldsm_x4t(uint32_t* r, uint32_t a) {
    asm volatile("ldmatrix.sync.aligned.m8n8.x4.trans.shared.b16 {%0,%1,%2,%3}, [%4];"
                 : "=r"(r[0]), "=r"(r[1]), "=r"(r[2]), "=r"(r[3]) : "r"(a));
}
#define CP16(dst, src)                                                         \
    asm volatile("cp.async.cg.shared.global [%0], [%1], 16;\n" :: "r"(dst), "l"(src))
#define CP_COMMIT() asm volatile("cp.async.commit_group;\n")
#define CP_WAIT0()  asm volatile("cp.async.wait_group 0;\n")
#define CP_WAIT1()  asm volatile("cp.async.wait_group 1;\n")

// ---------------- copy input -> g_x ----------------
__global__ void copy_kernel(const float* __restrict__ in, float* __restrict__ out, int n4) {
    int i = blockIdx.x * blockDim.x + threadIdx.x;
    if (i < n4) ((float4*)out)[i] = ((const float4*)in)[i];
}

// ---------------- fp32 -> bf16 weight conversion ----------------
__global__ void cvt_kernel(const float* __restrict__ in, __nv_bfloat16* __restrict__ out, int n4) {
    int i = blockIdx.x * blockDim.x + threadIdx.x;
    if (i < n4) {
        const float4 v = ((const float4*)in)[i];
        __nv_bfloat162 a = __floats2bfloat162_rn(v.x, v.y);
        __nv_bfloat162 b = __floats2bfloat162_rn(v.z, v.w);
        uint2 w; w.x = *(uint32_t*)&a; w.y = *(uint32_t*)&b;
        ((uint2*)out)[i] = w;
    }
}

// ---------------- layernorm: 1 block (256 thr) per row of 1024 -------------
__global__ void ln_kernel(const float* __restrict__ x, const float* __restrict__ w,
                          const float* __restrict__ b, __nv_bfloat16* __restrict__ o) {
    __shared__ float r1[8], r2[8];
    const int row = blockIdx.x, tid = threadIdx.x;
    const float4 v = *(const float4*)(x + (size_t)row * HH + tid * 4);
    float s = v.x + v.y + v.z + v.w;
    s = warp_sum(s);
    if ((tid & 31) == 0) r1[tid >> 5] = s;
    __syncthreads();
    float mean = 0.f;
#pragma unroll
    for (int i = 0; i < 8; i++) mean += r1[i];
    mean *= (1.f / (float)HH);
    const float d0 = v.x - mean, d1 = v.y - mean, d2 = v.z - mean, d3 = v.w - mean;
    float sq = d0 * d0 + d1 * d1 + d2 * d2 + d3 * d3;
    sq = warp_sum(sq);
    if ((tid & 31) == 0) r2[tid >> 5] = sq;
    __syncthreads();
    float var = 0.f;
#pragma unroll
    for (int i = 0; i < 8; i++) var += r2[i];
    var *= (1.f / (float)HH);
    const float rstd = rsqrtf(var + 1e-5f);
    const float4 wv = *(const float4*)(w + tid * 4);
    const float4 bv = *(const float4*)(b + tid * 4);
    __nv_bfloat162 o0 = __floats2bfloat162_rn(d0 * rstd * wv.x + bv.x, d1 * rstd * wv.y + bv.y);
    __nv_bfloat162 o1 = __floats2bfloat162_rn(d2 * rstd * wv.z + bv.z, d3 * rstd * wv.w + bv.w);
    uint2 pk; pk.x = *(uint32_t*)&o0; pk.y = *(uint32_t*)&o1;
    *(uint2*)(o + (size_t)row * HH + tid * 4) = pk;
}

// ---------------- bf16 tensor-core GEMM (TN) -------------------------------
// 128x128x64 CTA tile, 8 warps (2x4), 3-stage cp.async, swizzled ldmatrix.
// Rows are 64 bf16 = 128B = 8 chunks of 16B; chunk' = chunk ^ (row & 7).
#define GST    32768                 // bytes per stage (A 16KB + W 16KB)
#define GSMEM  (3*GST)

template <int EPI>
__global__ void __launch_bounds__(256, 2) mma_tn(
        const __nv_bfloat16* __restrict__ A, const __nv_bfloat16* __restrict__ W,
        const float* __restrict__ bias, const float* __restrict__ res,
        void* __restrict__ Cout, int M, int N, int K) {
    extern __shared__ uint8_t smraw[];
    const uint32_t smbase = (uint32_t)__cvta_generic_to_shared(smraw);
    const int tid = threadIdx.x;
    const int warp = tid >> 5, lane = tid & 31;
    const int wm = warp >> 2, wn = warp & 3;
    const int g = lane >> 2, t = lane & 3;
    const int mb = blockIdx.y << 7, nb = blockIdx.x << 7;

    // ---- staging geometry ----
    const int ra = tid >> 1, kc = (tid & 1) << 2;   // row, first chunk (0 or 4)
    const __nv_bfloat16* Ag = A + (size_t)(mb + ra) * K + kc * 8;
    const __nv_bfloat16* Wg = W + (size_t)(nb + ra) * K + kc * 8;
    uint32_t offA[4], offW[4];
#pragma unroll
    for (int i = 0; i < 4; i++) {
        const uint32_t o = ra * 128 + (((kc + i) ^ (ra & 7)) << 4);
        offA[i] = o; offW[i] = 16384 + o;
    }

    // ---- fragment addresses ----
    const uint32_t la7 = lane & 7, la15 = lane & 15;
    const uint32_t hiA = lane >> 4, hiB = (lane >> 3) & 1;
    const uint32_t aRow = (wm * 64 + la15) * 128;
    const uint32_t bRow = (wn * 32 + la7 + ((lane >> 4) << 3)) * 128;

    float acc[4][4][4];
#pragma unroll
    for (int a = 0; a < 4; a++)
#pragma unroll
        for (int b = 0; b < 4; b++)
#pragma unroll
            for (int c = 0; c < 4; c++) acc[a][b][c] = 0.f;

    const int nk = K >> 6;
    auto issue = [&](int kt, int s) {
        const __nv_bfloat16* ap = Ag + (kt << 6);
        const __nv_bfloat16* wp = Wg + (kt << 6);
        const uint32_t sb = smbase + (uint32_t)s * GST;
#pragma unroll
        for (int i = 0; i < 4; i++) {
            CP16(sb + offA[i], ap + i * 8);
            CP16(sb + offW[i], wp + i * 8);
        }
        CP_COMMIT();
    };

    issue(0, 0);
    issue(1, 1);

    int stage = 0;
    for (int kt = 0; kt < nk; ++kt) {
        if (kt == nk - 1) CP_WAIT0(); else CP_WAIT1();
        __syncthreads();
        if (kt + 2 < nk) {
            int ns = stage + 2; if (ns >= 3) ns -= 3;
            issue(kt + 2, ns);
        }
        const uint32_t sA = smbase + (uint32_t)stage * GST;
        const uint32_t sW = sA + 16384;
#pragma unroll
        for (int kk = 0; kk < 4; kk++) {
            const uint32_t swzA = (((2 * kk + hiA) ^ la7) << 4);
            const uint32_t swzB = (((2 * kk + hiB) ^ la7) << 4);
            uint32_t af[4][4], bf[4][4];
#pragma unroll
            for (int mt = 0; mt < 4; mt++)
                ldsm_x4(af[mt], sA + aRow + mt * 2048 + swzA);
#pragma unroll
            for (int p = 0; p < 2; p++)
                ldsm_x4(bf[p], sW + bRow + p * 2048 + swzB);
#pragma unroll
            for (int mt = 0; mt < 4; mt++)
#pragma unroll
                for (int nt = 0; nt < 4; nt++)
                    MMA_BF16(acc[mt][nt], af[mt][0], af[mt][1], af[mt][2], af[mt][3],
                             bf[nt >> 1][(nt & 1) * 2], bf[nt >> 1][(nt & 1) * 2 + 1]);
        }
        if (++stage == 3) stage = 0;
    }

    // epilogue: c0,c1 -> (row g, cols 2t,2t+1); c2,c3 -> (row g+8)
#pragma unroll
    for (int mt = 0; mt < 4; mt++) {
        const int r0 = mb + wm * 64 + mt * 16 + g;
#pragma unroll
        for (int nt = 0; nt < 4; nt++) {
            const int cb = nb + wn * 32 + nt * 8 + 2 * t;
            const float b0 = bias[cb], b1 = bias[cb + 1];
#pragma unroll
            for (int hh = 0; hh < 2; hh++) {
                const int rr = r0 + hh * 8;
                float v0 = acc[mt][nt][2 * hh + 0] + b0;
                float v1 = acc[mt][nt][2 * hh + 1] + b1;
                const size_t off = (size_t)rr * N + cb;
                if (EPI == 2) {
                    const float2 rv = *(const float2*)(res + off);
                    *(float2*)((float*)Cout + off) = make_float2(v0 + rv.x, v1 + rv.y);
                } else {
                    if (EPI == 1) { v0 = gelu_exact(v0); v1 = gelu_exact(v1); }
                    __nv_bfloat162 h2 = __floats2bfloat162_rn(v0, v1);
                    *(uint32_t*)((__nv_bfloat16*)Cout + off) = *(uint32_t*)&h2;
                }
            }
        }
    }
}

// ---------------- bf16 tensor-core flash attention (causal, ALiBi) ---------
// grid: (S/128, NH, B), 256 thr (8 warps x 16 q-rows). P kept in registers.
// smem: Q 16KB | 3 stages x (K 8KB + V 8KB + alibi 256B)
#define FSTG 16640
#define FLASH_SMEM (16384 + 3*FSTG)
__global__ void __launch_bounds__(256, 2) flash_kernel(
        const __nv_bfloat16* __restrict__ qkv, const float* __restrict__ alibi,
        __nv_bfloat16* __restrict__ ctx) {
    extern __shared__ uint8_t smraw[];
    const uint32_t smbase = (uint32_t)__cvta_generic_to_shared(smraw);
    uint32_t* smw = (uint32_t*)smraw;

    const int qt = blockIdx.x, hh = blockIdx.y, bb = blockIdx.z;
    const int tid = threadIdx.x;
    const int warp = tid >> 5, lane = tid & 31;
    const int g = lane >> 2, t = lane & 3;
    const int qbase = qt << 7;

    const __nv_bfloat16* qg  = qkv + (size_t)bb * SS * (3 * HH) + hh * DHH;
    const __nv_bfloat16* kg  = qg + HH;
    const __nv_bfloat16* vg  = qg + 2 * HH;
    const float* alg = alibi + ((size_t)bb * NHH + hh) * SS;

    // ---- KV staging geometry ----
    const int lrow = (tid & 127) >> 1, lkc = (tid & 1) << 2;
    const __nv_bfloat16* kvsrc = ((tid >= 128) ? vg : kg) + (size_t)lrow * (3 * HH) + lkc * 8;
    uint32_t offKV[4];
#pragma unroll
    for (int i = 0; i < 4; i++)
        offKV[i] = ((tid >= 128) ? 8192u : 0u) + lrow * 128 + (((lkc + i) ^ (lrow & 7)) << 4);

    auto issue = [&](int jt, int s) {
        const uint32_t sb = smbase + 16384 + (uint32_t)s * FSTG;
        const __nv_bfloat16* src = kvsrc + (size_t)(jt << 6) * (3 * HH);
#pragma unroll
        for (int i = 0; i < 4; i++) CP16(sb + offKV[i], src + i * 8);
        if (tid < 16) CP16(sb + 16384 + tid * 16, alg + (jt << 6) + tid * 4);
        CP_COMMIT();
    };

    // ---- load Q tile (swizzled) ----
    for (int f = tid; f < 1024; f += 256) {
        const int r = f >> 3, c = f & 7;
        const uint4 q4 = *(const uint4*)(qg + (size_t)(qbase + r) * (3 * HH) + c * 8);
        *(uint4*)(smw + r * 32 + ((c ^ (r & 7)) << 2)) = q4;
    }
    const int njt = 2 * qt + 2;
    issue(0, 0);
    issue(1, 1);
    __syncthreads();

    // ---- hoist Q fragments ----
    const uint32_t la7 = lane & 7, la15 = lane & 15;
    const uint32_t hiA = lane >> 4, hiB = (lane >> 3) & 1;
    const uint32_t qAddr = smbase + (warp * 16 + la15) * 128;
    uint32_t qf[4][4];
#pragma unroll
    for (int kk = 0; kk < 4; kk++)
        ldsm_x4(qf[kk], qAddr + (((2 * kk + hiA) ^ la7) << 4));

    // K fragment row base: row = (lane&7) + 8*(lane>>4) + p*16
    const uint32_t kRow = (la7 + ((lane >> 4) << 3)) * 128;
    // V (trans) key base: key = (lane&7) + 8*hiB + 16*kk ; chunk = 2p + (lane>>4)
    const uint32_t vKey = (la7 + (hiB << 3)) * 128;

    float mx[2] = { -INFINITY, -INFINITY };
    float lsum[2] = { 0.f, 0.f };
    float acc[8][4];
#pragma unroll
    for (int nt = 0; nt < 8; nt++)
#pragma unroll
        for (int c = 0; c < 4; c++) acc[nt][c] = 0.f;

    int stage = 0;
    for (int jt = 0; jt < njt; ++jt) {
        const int kbase = jt << 6;
        if (jt == njt - 1) CP_WAIT0(); else CP_WAIT1();
        __syncthreads();
        if (jt + 2 < njt) {
            int ns = stage + 2; if (ns >= 3) ns -= 3;
            issue(jt + 2, ns);
        }
        const uint32_t sK = smbase + 16384 + (uint32_t)stage * FSTG;
        const uint32_t sV = sK + 8192;
        const float* alS = (const float*)(smraw + 16384 + (size_t)stage * FSTG + 16384);

        // ---- S = Q K^T ----
        float s[8][4];
#pragma unroll
        for (int nt = 0; nt < 8; nt++)
#pragma unroll
            for (int c = 0; c < 4; c++) s[nt][c] = 0.f;
#pragma unroll
        for (int kk = 0; kk < 4; ++kk) {
            const uint32_t swzB = (((2 * kk + hiB) ^ la7) << 4);
            uint32_t kf[4][4];
#pragma unroll
            for (int p = 0; p < 4; p++)
                ldsm_x4(kf[p], sK + kRow + p * 2048 + swzB);
#pragma unroll
            for (int nt = 0; nt < 8; ++nt)
                MMA_BF16(s[nt], qf[kk][0], qf[kk][1], qf[kk][2], qf[kk][3],
                         kf[nt >> 1][(nt & 1) * 2], kf[nt >> 1][(nt & 1) * 2 + 1]);
        }

        // ---- online softmax; P -> registers (bf16 packed) ----
        const bool need_mask = (jt >= 2 * qt);
        uint32_t pr[8][2];
#pragma unroll
        for (int r = 0; r < 2; ++r) {
            const int qr = qbase + warp * 16 + g + r * 8;
            float rowmax = -INFINITY;
#pragma unroll
            for (int nt = 0; nt < 8; ++nt) {
#pragma unroll
                for (int c = 0; c < 2; ++c) {
                    const int col = nt * 8 + 2 * t + c;
                    float v = s[nt][r * 2 + c] * 0.125f + alS[col];
                    if (need_mask && (kbase + col > qr)) v = -1e30f;
                    s[nt][r * 2 + c] = v;
                    rowmax = fmaxf(rowmax, v);
                }
            }
            rowmax = fmaxf(rowmax, __shfl_xor_sync(0xffffffffu, rowmax, 1));
            rowmax = fmaxf(rowmax, __shfl_xor_sync(0xffffffffu, rowmax, 2));
            const float mn = fmaxf(mx[r], rowmax);
            const float corr = __expf(mx[r] - mn);
            mx[r] = mn;
            float rs = 0.f;
#pragma unroll
            for (int nt = 0; nt < 8; ++nt) {
                const float p0 = __expf(s[nt][r * 2 + 0] - mn);
                const float p1 = __expf(s[nt][r * 2 + 1] - mn);
                const __nv_bfloat162 h2 = __floats2bfloat162_rn(p0, p1);
                rs += __bfloat162float(h2.x) + __bfloat162float(h2.y);
                pr[nt][r] = *(const uint32_t*)&h2;
            }
            rs += __shfl_xor_sync(0xffffffffu, rs, 1);
            rs += __shfl_xor_sync(0xffffffffu, rs, 2);
            lsum[r] = lsum[r] * corr + rs;
#pragma unroll
            for (int nt = 0; nt < 8; ++nt) {
                acc[nt][r * 2 + 0] *= corr;
                acc[nt][r * 2 + 1] *= corr;
            }
        }

        // ---- O += P V (P from registers, V via ldmatrix.trans) ----
#pragma unroll
        for (int kk = 0; kk < 4; ++kk) {
            const uint32_t a0 = pr[2 * kk][0],     a1 = pr[2 * kk][1];
            const uint32_t a2 = pr[2 * kk + 1][0], a3 = pr[2 * kk + 1][1];
            const uint32_t vBase = sV + vKey + kk * 2048;   // 16 keys per kk
            uint32_t vf[4][4];
#pragma unroll
            for (int p = 0; p < 4; p++) {
                const uint32_t chunk = 2 * p + hiA;
                ldsm_x4t(vf[p], vBase + ((chunk ^ la7) << 4));
            }
#pragma unroll
            for (int nt = 0; nt < 8; ++nt)
                MMA_BF16(acc[nt], a0, a1, a2, a3,
                         vf[nt >> 1][(nt & 1) * 2], vf[nt >> 1][(nt & 1) * 2 + 1]);
        }
        if (++stage == 3) stage = 0;
    }

    // ---- write ctx (bf16) ----
    const float inv0 = 1.f / lsum[0], inv1 = 1.f / lsum[1];
    const int r0 = qbase + warp * 16 + g;
    __nv_bfloat16* o0 = ctx + ((size_t)bb * SS + r0) * HH + hh * DHH;
    __nv_bfloat16* o1 = o0 + (size_t)8 * HH;
#pragma unroll
    for (int nt = 0; nt < 8; ++nt) {
        const int col = nt * 8 + 2 * t;
        __nv_bfloat162 w0 = __floats2bfloat162_rn(acc[nt][0] * inv0, acc[nt][1] * inv0);
        __nv_bfloat162 w1 = __floats2bfloat162_rn(acc[nt][2] * inv1, acc[nt][3] * inv1);
        *(uint32_t*)(o0 + col) = *(uint32_t*)&w0;
        *(uint32_t*)(o1 + col) = *(uint32_t*)&w1;
    }
}

// ---------------- driver ----------------
extern "C" void kernel_launch(void* const* d_in, const int* in_sizes, int n_in,
                              void* d_out, int out_size) {
    const float* hs    = (const float*)d_in[0];
    const float* alibi = (const float*)d_in[1];
    const float* qkvw  = (const float*)d_in[2];
    const float* qkvb  = (const float*)d_in[3];
    const float* dw    = (const float*)d_in[4];
    const float* db    = (const float*)d_in[5];
    const float* w1    = (const float*)d_in[6];
    const float* b1    = (const float*)d_in[7];
    const float* w2    = (const float*)d_in[8];
    const float* b2    = (const float*)d_in[9];
    const float* l1w   = (const float*)d_in[10];
    const float* l1b   = (const float*)d_in[11];
    const float* l2w   = (const float*)d_in[12];
    const float* l2b   = (const float*)d_in[13];
    float* out = (float*)d_out;

    float *x;
    __nv_bfloat16 *h, *qkv, *ctx, *ff, *wr;
    cudaGetSymbolAddress((void**)&x,   g_x);
    cudaGetSymbolAddress((void**)&h,   g_h);
    cudaGetSymbolAddress((void**)&qkv, g_qkv);
    cudaGetSymbolAddress((void**)&ctx, g_ctx);
    cudaGetSymbolAddress((void**)&ff,  g_ff);
    cudaGetSymbolAddress((void**)&wr,  g_wr);

    cudaFuncSetAttribute(flash_kernel, cudaFuncAttributeMaxDynamicSharedMemorySize, FLASH_SMEM);
    cudaFuncSetAttribute(mma_tn<0>, cudaFuncAttributeMaxDynamicSharedMemorySize, GSMEM);
    cudaFuncSetAttribute(mma_tn<1>, cudaFuncAttributeMaxDynamicSharedMemorySize, GSMEM);
    cudaFuncSetAttribute(mma_tn<2>, cudaFuncAttributeMaxDynamicSharedMemorySize, GSMEM);

    const int n4 = MM * HH / 4;
    copy_kernel<<<(n4 + 255) / 256, 256>>>(hs, x, n4);

    // convert all weights to bf16 once (scratch g_wr)
    const size_t OFF_QKV = 0, OFF_D = 3145728, OFF_W1 = 4194304, OFF_W2 = 8388608;
    for (int l = 0; l < 2; ++l) {
        const size_t base = (size_t)l * LWF;
        struct { const float* s; size_t n; size_t o; } jobs[4] = {
            { qkvw + (size_t)l * 3 * HH * HH, (size_t)3 * HH * HH, base + OFF_QKV },
            { dw   + (size_t)l * HH * HH,     (size_t)HH * HH,     base + OFF_D   },
            { w1   + (size_t)l * FFD * HH,    (size_t)FFD * HH,    base + OFF_W1  },
            { w2   + (size_t)l * HH * FFD,    (size_t)HH * FFD,    base + OFF_W2  },
        };
        for (int j = 0; j < 4; ++j) {
            const int m4 = (int)(jobs[j].n / 4);
            cvt_kernel<<<(m4 + 255) / 256, 256>>>(jobs[j].s, wr + jobs[j].o, m4);
        }
    }

    for (int l = 0; l < 2; ++l) {
        const size_t base = (size_t)l * LWF;
        ln_kernel<<<MM, 256>>>(x, l1w + l * HH, l1b + l * HH, h);
        mma_tn<0><<<dim3(3 * HH / 128, MM / 128), 256, GSMEM>>>(
            h, wr + base + OFF_QKV, qkvb + (size_t)l * 3 * HH, nullptr,
            qkv, MM, 3 * HH, HH);
        flash_kernel<<<dim3(SS / 128, NHH, BB), 256, FLASH_SMEM>>>(qkv, alibi, ctx);
        mma_tn<2><<<dim3(HH / 128, MM / 128), 256, GSMEM>>>(
            ctx, wr + base + OFF_D, db + (size_t)l * HH, x,
            x, MM, HH, HH);
        ln_kernel<<<MM, 256>>>(x, l2w + l * HH, l2b + l * HH, h);
        mma_tn<1><<<dim3(FFD / 128, MM / 128), 256, GSMEM>>>(
            h, wr + base + OFF_W1, b1 + (size_t)l * FFD, nullptr,
            ff, MM, FFD, HH);
        mma_tn<2><<<dim3(HH / 128, MM / 128), 256, GSMEM>>>(
            ff, wr + base + OFF_W2, b2 + (size_t)l * HH, x,
            (l == 1) ? out : x, MM, HH, FFD);
    }
}